// round 1
// baseline (speedup 1.0000x reference)
#include <cuda_runtime.h>

#define BATCH 4
#define CHN   256
#define CQKD  64
#define HH    64
#define WW    64
#define HWSZ  4096

// Scratch for conv outputs (device globals — no allocation allowed in kernel_launch)
__device__ float g_q[BATCH * CQKD * HWSZ];   // [b][d][hw]
__device__ float g_k[BATCH * CQKD * HWSZ];   // [b][d][hw]
__device__ float g_v[BATCH * CHN  * HWSZ];   // [b][c][hw]

// ---------------------------------------------------------------------------
// 3x3 conv, pad 1, direct, smem-tiled.
// block: 256 threads laid out 32(x) x 8(y); each thread computes 4 rows
// (stride 8) x 1 col x OCB output channels -> 32x32 spatial tile per block.
// grid: (W/32, H/32, B * O/OCB)
// ---------------------------------------------------------------------------
constexpr int CIC = 8;   // input channels per smem chunk
constexpr int OCB = 8;   // output channels per block

__global__ __launch_bounds__(256)
void conv3x3_kernel(const float* __restrict__ x,
                    const float* __restrict__ wgt,
                    const float* __restrict__ bias,
                    int Ototal, int which)
{
    __shared__ float xs[CIC][34][34];
    __shared__ float ws[OCB][CIC][9];

    float* outg = (which == 0) ? g_q : (which == 1) ? g_k : g_v;

    const int t   = threadIdx.x;
    const int txx = t & 31;
    const int tyy = t >> 5;
    const int x0  = blockIdx.x * 32;
    const int y0  = blockIdx.y * 32;
    const int nOB = Ototal / OCB;
    const int b   = blockIdx.z / nOB;
    const int o0  = (blockIdx.z % nOB) * OCB;

    const float* xb = x + (size_t)b * CHN * HWSZ;

    float acc[4][OCB];
    #pragma unroll
    for (int s = 0; s < 4; s++)
        #pragma unroll
        for (int o = 0; o < OCB; o++) acc[s][o] = 0.f;

    float* wsf = &ws[0][0][0];

    for (int c0 = 0; c0 < CHN; c0 += CIC) {
        // load input tile with halo: rows [y0-1, y0+32], cols [x0-1, x0+32]
        for (int idx = t; idx < CIC * 34 * 34; idx += 256) {
            int ci = idx / 1156;
            int r  = idx - ci * 1156;
            int yy = r / 34;
            int xx = r - yy * 34;
            int gy = y0 - 1 + yy;
            int gx = x0 - 1 + xx;
            float v = 0.f;
            if (gy >= 0 && gy < HH && gx >= 0 && gx < WW)
                v = xb[(size_t)(c0 + ci) * HWSZ + gy * WW + gx];
            xs[ci][yy][xx] = v;
        }
        // load weights [OCB][CIC][9]
        for (int idx = t; idx < OCB * CIC * 9; idx += 256) {
            int o = idx / (CIC * 9);
            int r = idx - o * (CIC * 9);
            wsf[idx] = wgt[(size_t)(o0 + o) * CHN * 9 + (size_t)c0 * 9 + r];
        }
        __syncthreads();

        for (int ci = 0; ci < CIC; ci++) {
            #pragma unroll
            for (int ky = 0; ky < 3; ky++)
                #pragma unroll
                for (int kx = 0; kx < 3; kx++) {
                    float wv[OCB];
                    #pragma unroll
                    for (int o = 0; o < OCB; o++) wv[o] = ws[o][ci][ky * 3 + kx];
                    #pragma unroll
                    for (int s = 0; s < 4; s++) {
                        float xv = xs[ci][tyy + s * 8 + ky][txx + kx];
                        #pragma unroll
                        for (int o = 0; o < OCB; o++)
                            acc[s][o] += wv[o] * xv;
                    }
                }
        }
        __syncthreads();
    }

    #pragma unroll
    for (int o = 0; o < OCB; o++) {
        float bo = bias[o0 + o];
        #pragma unroll
        for (int s = 0; s < 4; s++) {
            int gy = y0 + tyy + s * 8;
            outg[((size_t)b * Ototal + o0 + o) * HWSZ + gy * WW + x0 + txx] =
                acc[s][o] + bo;
        }
    }
}

// ---------------------------------------------------------------------------
// Fused flash attention: softmax(q^T k * scale) applied to v, streamed over j.
// block = 256 threads, handles one (batch, 32-row i-tile).
// grid: (HW/32, B)
// ---------------------------------------------------------------------------
__global__ __launch_bounds__(256)
void attn_kernel(float* __restrict__ out)
{
    extern __shared__ float sm[];
    float* vs   = sm;                 // [64][256]  (16B-aligned for float4)
    float* qs   = sm + 64 * 256;      // [32][65]   q tile, pre-scaled
    float* ks   = qs + 32 * 65;       // [64][65]
    float* ps   = ks + 64 * 65;       // [32][65]   exp(scores)
    float* mrow = ps + 32 * 65;       // [32] running max
    float* lrow = mrow + 32;          // [32] running denom
    float* arow = lrow + 32;          // [32] per-tile rescale

    const int t  = threadIdx.x;
    const int b  = blockIdx.y;
    const int i0 = blockIdx.x * 32;

    const float* qg = g_q + (size_t)b * CQKD * HWSZ;
    const float* kg = g_k + (size_t)b * CQKD * HWSZ;
    const float* vg = g_v + (size_t)b * CHN * HWSZ;

    // load q tile transposed ([i][d]), fold in scale = CQK^-0.5 = 0.125
    for (int idx = t; idx < 32 * 64; idx += 256) {
        int i = idx & 31, d = idx >> 5;
        qs[i * 65 + d] = qg[d * HWSZ + i0 + i] * 0.125f;
    }
    if (t < 32) { mrow[t] = -1e30f; lrow[t] = 0.f; }

    // score mapping: 16-lane groups; group g handles rows 2g, 2g+1;
    // lane u in group handles j in {u, u+16, u+32, u+48}
    const int u  = t & 15;
    const int ii = (t >> 4) * 2;
    // AV mapping: thread owns row ti and 32 channels c = cl*4 + c4*32 + e
    const int ti = t >> 3;
    const int cl = t & 7;

    float acc[32];
    #pragma unroll
    for (int r = 0; r < 32; r++) acc[r] = 0.f;

    for (int j0 = 0; j0 < HWSZ; j0 += 64) {
        __syncthreads();  // previous AV done, qs ready
        // load k tile transposed: ks[j][d] (coalesced over j)
        for (int idx = t; idx < 64 * 64; idx += 256) {
            int j = idx & 63, d = idx >> 6;
            ks[j * 65 + d] = kg[d * HWSZ + j0 + j];
        }
        // load v tile transposed: vs[j][c] (coalesced over j)
        for (int idx = t; idx < 64 * 256; idx += 256) {
            int j = idx & 63, c = idx >> 6;
            vs[j * 256 + c] = vg[c * HWSZ + j0 + j];
        }
        __syncthreads();

        // ---- scores: s[i][j] = sum_d q[i][d] * k[j][d] ----
        float s0[4] = {0.f, 0.f, 0.f, 0.f};
        float s1[4] = {0.f, 0.f, 0.f, 0.f};
        #pragma unroll 8
        for (int d = 0; d < 64; d++) {
            float qa = qs[ii * 65 + d];
            float qb = qs[(ii + 1) * 65 + d];
            #pragma unroll
            for (int n = 0; n < 4; n++) {
                float kv = ks[(u + 16 * n) * 65 + d];
                s0[n] += qa * kv;
                s1[n] += qb * kv;
            }
        }

        // ---- online softmax over the 16-lane group ----
        float m0 = fmaxf(fmaxf(s0[0], s0[1]), fmaxf(s0[2], s0[3]));
        float m1 = fmaxf(fmaxf(s1[0], s1[1]), fmaxf(s1[2], s1[3]));
        #pragma unroll
        for (int off = 8; off > 0; off >>= 1) {
            m0 = fmaxf(m0, __shfl_xor_sync(0xffffffffu, m0, off));
            m1 = fmaxf(m1, __shfl_xor_sync(0xffffffffu, m1, off));
        }
        float mo0 = mrow[ii], mo1 = mrow[ii + 1];
        float mn0 = fmaxf(mo0, m0), mn1 = fmaxf(mo1, m1);
        float l0 = 0.f, l1 = 0.f;
        #pragma unroll
        for (int n = 0; n < 4; n++) {
            float e0 = __expf(s0[n] - mn0);
            float e1 = __expf(s1[n] - mn1);
            ps[ii * 65 + u + 16 * n]       = e0;
            ps[(ii + 1) * 65 + u + 16 * n] = e1;
            l0 += e0; l1 += e1;
        }
        #pragma unroll
        for (int off = 8; off > 0; off >>= 1) {
            l0 += __shfl_xor_sync(0xffffffffu, l0, off);
            l1 += __shfl_xor_sync(0xffffffffu, l1, off);
        }
        float a0 = __expf(mo0 - mn0);
        float a1 = __expf(mo1 - mn1);
        if (u == 0) {
            mrow[ii]     = mn0;
            mrow[ii + 1] = mn1;
            lrow[ii]     = lrow[ii]     * a0 + l0;
            lrow[ii + 1] = lrow[ii + 1] * a1 + l1;
            arow[ii]     = a0;
            arow[ii + 1] = a1;
        }
        __syncthreads();  // ps / arow ready

        // ---- AV: acc[c] = acc[c]*alpha + sum_j p[ti][j] * v[c][j] ----
        float al = arow[ti];
        #pragma unroll
        for (int r = 0; r < 32; r++) acc[r] *= al;
        const float4* vs4 = (const float4*)vs;
        #pragma unroll 4
        for (int j = 0; j < 64; j++) {
            float p = ps[ti * 65 + j];
            #pragma unroll
            for (int c4 = 0; c4 < 8; c4++) {
                float4 v4 = vs4[j * 64 + cl + c4 * 8];
                acc[c4 * 4 + 0] += v4.x * p;
                acc[c4 * 4 + 1] += v4.y * p;
                acc[c4 * 4 + 2] += v4.z * p;
                acc[c4 * 4 + 3] += v4.w * p;
            }
        }
    }

    // ---- epilogue: normalize and write out[b][c][i] ----
    float rl = 1.f / lrow[ti];
    #pragma unroll
    for (int c4 = 0; c4 < 8; c4++) {
        int c = cl * 4 + c4 * 32;
        #pragma unroll
        for (int e = 0; e < 4; e++)
            out[((size_t)b * CHN + c + e) * HWSZ + i0 + ti] = acc[c4 * 4 + e] * rl;
    }
}

// ---------------------------------------------------------------------------

static constexpr int ATTN_SMEM = (64 * 256 + 32 * 65 + 64 * 65 + 32 * 65 + 96) * 4;

extern "C" void kernel_launch(void* const* d_in, const int* in_sizes, int n_in,
                              void* d_out, int out_size)
{
    const float* x   = (const float*)d_in[0];
    const float* q_w = (const float*)d_in[1];
    const float* q_b = (const float*)d_in[2];
    const float* k_w = (const float*)d_in[3];
    const float* k_b = (const float*)d_in[4];
    const float* v_w = (const float*)d_in[5];
    const float* v_b = (const float*)d_in[6];
    float* out = (float*)d_out;

    // idempotent, cheap; not a stream op
    cudaFuncSetAttribute(attn_kernel,
                         cudaFuncAttributeMaxDynamicSharedMemorySize, ATTN_SMEM);

    dim3 blk(256);
    conv3x3_kernel<<<dim3(2, 2, BATCH * (CQKD / OCB)), blk>>>(x, q_w, q_b, CQKD, 0);
    conv3x3_kernel<<<dim3(2, 2, BATCH * (CQKD / OCB)), blk>>>(x, k_w, k_b, CQKD, 1);
    conv3x3_kernel<<<dim3(2, 2, BATCH * (CHN  / OCB)), blk>>>(x, v_w, v_b, CHN, 2);
    attn_kernel<<<dim3(HWSZ / 32, BATCH), blk, ATTN_SMEM>>>(out);
}

// round 2
// speedup vs baseline: 2.0864x; 2.0864x over previous
#include <cuda_runtime.h>

#define BATCH 4
#define CHN   256
#define CQKD  64
#define HH    64
#define WW    64
#define HWSZ  4096

__device__ float g_q[BATCH * CQKD * HWSZ];   // [b][d][hw]
__device__ float g_k[BATCH * CQKD * HWSZ];   // [b][d][hw]
__device__ float g_v[BATCH * CHN  * HWSZ];   // [b][c][hw]

typedef unsigned long long u64;

__device__ __forceinline__ u64 pk2(float lo, float hi) {
    u64 r; asm("mov.b64 %0, {%1, %2};" : "=l"(r) : "f"(lo), "f"(hi)); return r;
}
__device__ __forceinline__ float2 upk2(u64 v) {
    float2 f; asm("mov.b64 {%0, %1}, %2;" : "=f"(f.x), "=f"(f.y) : "l"(v)); return f;
}
__device__ __forceinline__ void fma2(u64& d, u64 a, u64 b) {
    asm("fma.rn.f32x2 %0, %1, %2, %0;" : "+l"(d) : "l"(a), "l"(b));
}
__device__ __forceinline__ void mul2(u64& d, u64 a) {
    asm("mul.rn.f32x2 %0, %0, %1;" : "+l"(d) : "l"(a));
}

// ---------------------------------------------------------------------------
// 3x3 conv, pad 1. One launch covers q (oc 0-63), k (64-127), v (128-383).
// block: 256 threads (32x x 8y); thread computes 4 rows x 1 col x 16 oc.
// grid: (2, 2, B*24)
// ---------------------------------------------------------------------------
constexpr int OCB = 16;

__global__ __launch_bounds__(256)
void conv3x3_all(const float* __restrict__ x,
                 const float* __restrict__ qw, const float* __restrict__ qb,
                 const float* __restrict__ kw, const float* __restrict__ kb,
                 const float* __restrict__ vw, const float* __restrict__ vb)
{
    __shared__ float xs[8][34][34];
    __shared__ __align__(16) float ws[8 * 9 * OCB];   // [ci][k][o] (o innermost)

    const int t   = threadIdx.x;
    const int txx = t & 31;
    const int tyy = t >> 5;
    const int x0  = blockIdx.x * 32;
    const int y0  = blockIdx.y * 32;
    const int b   = blockIdx.z / 24;
    const int og  = (blockIdx.z % 24) * OCB;

    const float* wgt; const float* bias; float* outg; int o0, Ot;
    if (og < 64)       { wgt = qw; bias = qb; outg = g_q; o0 = og;       Ot = 64;  }
    else if (og < 128) { wgt = kw; bias = kb; outg = g_k; o0 = og - 64;  Ot = 64;  }
    else               { wgt = vw; bias = vb; outg = g_v; o0 = og - 128; Ot = 256; }

    const float* xb = x + (size_t)b * CHN * HWSZ;

    u64 acc2[4][OCB / 2];
    #pragma unroll
    for (int s = 0; s < 4; s++)
        #pragma unroll
        for (int oo = 0; oo < OCB / 2; oo++) acc2[s][oo] = 0ull;

    for (int c0 = 0; c0 < CHN; c0 += 8) {
        for (int idx = t; idx < 8 * 34 * 34; idx += 256) {
            int ci = idx / 1156;
            int r  = idx - ci * 1156;
            int yy = r / 34;
            int xx = r - yy * 34;
            int gy = y0 - 1 + yy;
            int gx = x0 - 1 + xx;
            float v = 0.f;
            if ((unsigned)gy < HH && (unsigned)gx < WW)
                v = xb[(size_t)(c0 + ci) * HWSZ + gy * WW + gx];
            xs[ci][yy][xx] = v;
        }
        for (int idx = t; idx < 8 * 9 * OCB; idx += 256) {
            int o = idx & (OCB - 1);
            int r = idx >> 4;          // ci*9 + k
            int ci = r / 9;
            int kk = r - ci * 9;
            ws[r * OCB + o] = wgt[(size_t)(o0 + o) * (CHN * 9) + (size_t)(c0 + ci) * 9 + kk];
        }
        __syncthreads();

        for (int ci = 0; ci < 8; ci++) {
            #pragma unroll
            for (int ky = 0; ky < 3; ky++)
                #pragma unroll
                for (int kx = 0; kx < 3; kx++) {
                    const u64* wp = (const u64*)&ws[(ci * 9 + ky * 3 + kx) * OCB];
                    u64 wv[OCB / 2];
                    #pragma unroll
                    for (int oo = 0; oo < OCB / 2; oo++) wv[oo] = wp[oo];
                    #pragma unroll
                    for (int s = 0; s < 4; s++) {
                        float xv = xs[ci][tyy + s * 8 + ky][txx + kx];
                        u64 xv2 = pk2(xv, xv);
                        #pragma unroll
                        for (int oo = 0; oo < OCB / 2; oo++)
                            fma2(acc2[s][oo], xv2, wv[oo]);
                    }
                }
        }
        __syncthreads();
    }

    #pragma unroll
    for (int oo = 0; oo < OCB / 2; oo++) {
        float b0 = bias[o0 + 2 * oo];
        float b1 = bias[o0 + 2 * oo + 1];
        #pragma unroll
        for (int s = 0; s < 4; s++) {
            float2 f = upk2(acc2[s][oo]);
            int gy = y0 + tyy + s * 8;
            size_t base = ((size_t)b * Ot + o0) * HWSZ + (size_t)gy * WW + x0 + txx;
            outg[base + (size_t)(2 * oo)     * HWSZ] = f.x + b0;
            outg[base + (size_t)(2 * oo + 1) * HWSZ] = f.y + b1;
        }
    }
}

// ---------------------------------------------------------------------------
// Fused flash attention. i-tile = 64, j-tile = 64, 256 threads.
// grid: (HW/64, B)
// smem: vs [256][68] (v, [c][j]), qs [64][64] ([i][d]), ks [64][64] ([d][j]),
//       ps [64][64] ([i][j]), stats.
// Score map: 16-lane group g -> rows 4g..4g+3; lane u -> j = 4u..4u+3.
// AV map:    warp rg -> rows 8rg..8rg+7; lane cg -> channels {cg+32k}.
// ---------------------------------------------------------------------------
__global__ __launch_bounds__(256)
void attn_kernel(float* __restrict__ out)
{
    extern __shared__ float sm[];
    float* vs   = sm;                  // 256*68
    float* qs   = vs + 256 * 68;       // 64*64
    float* ks   = qs + 64 * 64;        // 64*64
    float* ps   = ks + 64 * 64;        // 64*64
    float* mrow = ps + 64 * 64;        // 64
    float* lrow = mrow + 64;           // 64
    float* arow = lrow + 64;           // 64

    const int t  = threadIdx.x;
    const int b  = blockIdx.y;
    const int i0 = blockIdx.x * 64;

    const float* qg = g_q + (size_t)b * CQKD * HWSZ;
    const float* kg = g_k + (size_t)b * CQKD * HWSZ;
    const float* vg = g_v + (size_t)b * CHN * HWSZ;

    // q tile [i][d], pre-scaled (once per block; write conflicts are amortized)
    for (int idx = t; idx < 64 * 64; idx += 256) {
        int i = idx & 63, d = idx >> 6;
        qs[i * 64 + d] = qg[(size_t)d * HWSZ + i0 + i] * 0.125f;
    }
    if (t < 64) { mrow[t] = -1e30f; lrow[t] = 0.f; arow[t] = 0.f; }

    const int u  = t & 15, g  = t >> 4;
    const int cg = t & 31, rg = t >> 5;

    u64 acc2[8][4];   // rows 8rg+r, channel pair (cg+32kk, cg+32(kk+4))
    #pragma unroll
    for (int r = 0; r < 8; r++)
        #pragma unroll
        for (int kk = 0; kk < 4; kk++) acc2[r][kk] = 0ull;

    for (int j0 = 0; j0 < HWSZ; j0 += 64) {
        __syncthreads();   // prev AV done with ps/vs; qs stable

        // k tile: ks[d][j] — straight coalesced copy
        for (int idx = t; idx < 1024; idx += 256) {
            int jq = idx & 15, d = idx >> 4;
            *(float4*)(ks + d * 64 + jq * 4) =
                *(const float4*)(kg + (size_t)d * HWSZ + j0 + jq * 4);
        }
        // v tile: vs[c][j], stride 68 — conflict-free stores & loads
        for (int idx = t; idx < 4096; idx += 256) {
            int jq = idx & 15, c = idx >> 4;
            *(float4*)(vs + c * 68 + jq * 4) =
                *(const float4*)(vg + (size_t)c * HWSZ + j0 + jq * 4);
        }
        __syncthreads();

        // ---- scores: s[r][jj] = sum_d q[4g+r][d] * k[d][4u+jj] ----
        float s[4][4];
        #pragma unroll
        for (int r = 0; r < 4; r++)
            #pragma unroll
            for (int jj = 0; jj < 4; jj++) s[r][jj] = 0.f;

        #pragma unroll 2
        for (int d4 = 0; d4 < 16; d4++) {
            float4 k0 = *(const float4*)(ks + (4 * d4 + 0) * 64 + 4 * u);
            float4 k1 = *(const float4*)(ks + (4 * d4 + 1) * 64 + 4 * u);
            float4 k2 = *(const float4*)(ks + (4 * d4 + 2) * 64 + 4 * u);
            float4 k3 = *(const float4*)(ks + (4 * d4 + 3) * 64 + 4 * u);
            #pragma unroll
            for (int r = 0; r < 4; r++) {
                float4 qv = *(const float4*)(qs + (4 * g + r) * 64 + 4 * d4);
                s[r][0] += qv.x * k0.x + qv.y * k1.x + qv.z * k2.x + qv.w * k3.x;
                s[r][1] += qv.x * k0.y + qv.y * k1.y + qv.z * k2.y + qv.w * k3.y;
                s[r][2] += qv.x * k0.z + qv.y * k1.z + qv.z * k2.z + qv.w * k3.z;
                s[r][3] += qv.x * k0.w + qv.y * k1.w + qv.z * k2.w + qv.w * k3.w;
            }
        }

        // ---- online softmax (per 16-lane group, 4 rows) ----
        #pragma unroll
        for (int r = 0; r < 4; r++) {
            int row = 4 * g + r;
            float mx = fmaxf(fmaxf(s[r][0], s[r][1]), fmaxf(s[r][2], s[r][3]));
            #pragma unroll
            for (int off = 8; off; off >>= 1)
                mx = fmaxf(mx, __shfl_xor_sync(0xffffffffu, mx, off));
            float mo = mrow[row];
            float mn = fmaxf(mo, mx);
            float e0 = __expf(s[r][0] - mn);
            float e1 = __expf(s[r][1] - mn);
            float e2 = __expf(s[r][2] - mn);
            float e3 = __expf(s[r][3] - mn);
            *(float4*)(ps + row * 64 + 4 * u) = make_float4(e0, e1, e2, e3);
            float l = e0 + e1 + e2 + e3;
            #pragma unroll
            for (int off = 8; off; off >>= 1)
                l += __shfl_xor_sync(0xffffffffu, l, off);
            if (u == 0) {
                float a = __expf(mo - mn);
                mrow[row] = mn;
                arow[row] = a;
                lrow[row] = lrow[row] * a + l;
            }
        }
        __syncthreads();   // ps / arow ready

        // ---- rescale accumulators ----
        #pragma unroll
        for (int r = 0; r < 8; r++) {
            float a = arow[8 * rg + r];
            u64 a2 = pk2(a, a);
            #pragma unroll
            for (int kk = 0; kk < 4; kk++) mul2(acc2[r][kk], a2);
        }

        // ---- AV: acc[r][c] += sum_j p[row][j] * v[c][j] (packed f32x2) ----
        #pragma unroll 2
        for (int j4 = 0; j4 < 16; j4++) {
            u64 vv[4][4];
            #pragma unroll
            for (int kk = 0; kk < 4; kk++) {
                float4 va = *(const float4*)(vs + (cg + 32 * kk)       * 68 + 4 * j4);
                float4 vb = *(const float4*)(vs + (cg + 32 * (kk + 4)) * 68 + 4 * j4);
                vv[kk][0] = pk2(va.x, vb.x);
                vv[kk][1] = pk2(va.y, vb.y);
                vv[kk][2] = pk2(va.z, vb.z);
                vv[kk][3] = pk2(va.w, vb.w);
            }
            #pragma unroll
            for (int r = 0; r < 8; r++) {
                float4 p = *(const float4*)(ps + (8 * rg + r) * 64 + 4 * j4);
                u64 p0 = pk2(p.x, p.x), p1 = pk2(p.y, p.y);
                u64 p2 = pk2(p.z, p.z), p3 = pk2(p.w, p.w);
                #pragma unroll
                for (int kk = 0; kk < 4; kk++) {
                    fma2(acc2[r][kk], p0, vv[kk][0]);
                    fma2(acc2[r][kk], p1, vv[kk][1]);
                    fma2(acc2[r][kk], p2, vv[kk][2]);
                    fma2(acc2[r][kk], p3, vv[kk][3]);
                }
            }
        }
    }

    // ---- epilogue: normalize, transpose through smem, coalesced stores ----
    __syncthreads();
    #pragma unroll
    for (int r = 0; r < 8; r++) {
        float rl = 1.f / lrow[8 * rg + r];
        #pragma unroll
        for (int kk = 0; kk < 4; kk++) {
            float2 f = upk2(acc2[r][kk]);
            vs[(cg + 32 * kk)       * 68 + 8 * rg + r] = f.x * rl;
            vs[(cg + 32 * (kk + 4)) * 68 + 8 * rg + r] = f.y * rl;
        }
    }
    __syncthreads();
    for (int idx = t; idx < 4096; idx += 256) {
        int iq = idx & 15, c = idx >> 4;
        *(float4*)(out + ((size_t)b * CHN + c) * HWSZ + i0 + 4 * iq) =
            *(const float4*)(vs + c * 68 + 4 * iq);
    }
}

// ---------------------------------------------------------------------------

static constexpr int ATTN_SMEM = (256 * 68 + 3 * 64 * 64 + 192) * 4;  // 119552 B

extern "C" void kernel_launch(void* const* d_in, const int* in_sizes, int n_in,
                              void* d_out, int out_size)
{
    const float* x   = (const float*)d_in[0];
    const float* q_w = (const float*)d_in[1];
    const float* q_b = (const float*)d_in[2];
    const float* k_w = (const float*)d_in[3];
    const float* k_b = (const float*)d_in[4];
    const float* v_w = (const float*)d_in[5];
    const float* v_b = (const float*)d_in[6];
    float* out = (float*)d_out;

    cudaFuncSetAttribute(attn_kernel,
                         cudaFuncAttributeMaxDynamicSharedMemorySize, ATTN_SMEM);

    conv3x3_all<<<dim3(2, 2, BATCH * 24), 256>>>(x, q_w, q_b, k_w, k_b, v_w, v_b);
    attn_kernel<<<dim3(HWSZ / 64, BATCH), 256, ATTN_SMEM>>>(out);
}

// round 4
// speedup vs baseline: 4.5154x; 2.1642x over previous
#include <cuda_runtime.h>
#include <cstdint>

#define BATCH 4
#define CHN   256
#define CQKD  64
#define HH    64
#define WW    64
#define HWSZ  4096

// conv outputs (tf32-rounded fp32)
__device__ float g_qT[BATCH * HWSZ * CQKD];            // [b][hw][d], pre-scaled 0.125
__device__ float g_kT[BATCH * HWSZ * CQKD];            // [b][hw][d]
__device__ float g_v [BATCH * CHN  * HWSZ];            // [b][c][hw]
// attention matrix scratch (logits, then tf32 probs in-place)
__device__ float g_s [(size_t)BATCH * HWSZ * HWSZ];    // [b][i][j]

typedef unsigned long long u64;

// ---------------- helpers ----------------
__device__ __forceinline__ u64 pk2(float lo, float hi) {
    u64 r; asm("mov.b64 %0, {%1, %2};" : "=l"(r) : "f"(lo), "f"(hi)); return r;
}
__device__ __forceinline__ float2 upk2(u64 v) {
    float2 f; asm("mov.b64 {%0, %1}, %2;" : "=f"(f.x), "=f"(f.y) : "l"(v)); return f;
}
__device__ __forceinline__ void fma2(u64& d, u64 a, u64 b) {
    asm("fma.rn.f32x2 %0, %1, %2, %0;" : "+l"(d) : "l"(a), "l"(b));
}
__device__ __forceinline__ float tf32r(float x) {
    uint32_t b; asm("cvt.rna.tf32.f32 %0, %1;" : "=r"(b) : "f"(x));
    return __uint_as_float(b);
}
__device__ __forceinline__ void mma8(float* c, const uint32_t* a,
                                     uint32_t b0, uint32_t b1) {
    asm volatile("mma.sync.aligned.m16n8k8.row.col.f32.tf32.tf32.f32 "
        "{%0,%1,%2,%3}, {%4,%5,%6,%7}, {%8,%9}, {%0,%1,%2,%3};"
        : "+f"(c[0]), "+f"(c[1]), "+f"(c[2]), "+f"(c[3])
        : "r"(a[0]), "r"(a[1]), "r"(a[2]), "r"(a[3]), "r"(b0), "r"(b1));
}
__device__ __forceinline__ void cpa16(uint32_t saddr, const float* g) {
    asm volatile("cp.async.cg.shared.global [%0], [%1], 16;"
                 :: "r"(saddr), "l"(g) : "memory");
}
__device__ __forceinline__ uint32_t smem_u32(const void* p) {
    return (uint32_t)__cvta_generic_to_shared((void*)p);
}

// ---------------------------------------------------------------------------
// 3x3 conv, pad 1, fp32 SIMT with f32x2. q/k transposed [b][hw][d]; all
// outputs tf32-rounded so the GEMM kernels can feed mma.sync directly.
// ---------------------------------------------------------------------------
constexpr int OCB = 16;

__global__ __launch_bounds__(256)
void conv3x3_all(const float* __restrict__ x,
                 const float* __restrict__ qw, const float* __restrict__ qb,
                 const float* __restrict__ kw, const float* __restrict__ kb,
                 const float* __restrict__ vw, const float* __restrict__ vb)
{
    __shared__ float xs[8][34][34];
    __shared__ __align__(16) float ws[8 * 9 * OCB];

    const int t   = threadIdx.x;
    const int txx = t & 31;
    const int tyy = t >> 5;
    const int x0  = blockIdx.x * 32;
    const int y0  = blockIdx.y * 32;
    const int b   = blockIdx.z / 24;
    const int og  = (blockIdx.z % 24) * OCB;

    const float* wgt; const float* bias; int o0, kind;
    if (og < 64)       { wgt = qw; bias = qb; o0 = og;       kind = 0; }
    else if (og < 128) { wgt = kw; bias = kb; o0 = og - 64;  kind = 1; }
    else               { wgt = vw; bias = vb; o0 = og - 128; kind = 2; }

    const float* xb = x + (size_t)b * CHN * HWSZ;

    u64 acc2[4][OCB / 2];
    #pragma unroll
    for (int s = 0; s < 4; s++)
        #pragma unroll
        for (int oo = 0; oo < OCB / 2; oo++) acc2[s][oo] = 0ull;

    for (int c0 = 0; c0 < CHN; c0 += 8) {
        for (int idx = t; idx < 8 * 34 * 34; idx += 256) {
            int ci = idx / 1156;
            int r  = idx - ci * 1156;
            int yy = r / 34;
            int xx = r - yy * 34;
            int gy = y0 - 1 + yy;
            int gx = x0 - 1 + xx;
            float v = 0.f;
            if ((unsigned)gy < HH && (unsigned)gx < WW)
                v = xb[(size_t)(c0 + ci) * HWSZ + gy * WW + gx];
            xs[ci][yy][xx] = v;
        }
        for (int idx = t; idx < 8 * 9 * OCB; idx += 256) {
            int o = idx & (OCB - 1);
            int r = idx >> 4;
            int ci = r / 9;
            int kk = r - ci * 9;
            ws[r * OCB + o] = wgt[(size_t)(o0 + o) * (CHN * 9) + (size_t)(c0 + ci) * 9 + kk];
        }
        __syncthreads();

        for (int ci = 0; ci < 8; ci++) {
            #pragma unroll
            for (int ky = 0; ky < 3; ky++)
                #pragma unroll
                for (int kx = 0; kx < 3; kx++) {
                    const u64* wp = (const u64*)&ws[(ci * 9 + ky * 3 + kx) * OCB];
                    u64 wv[OCB / 2];
                    #pragma unroll
                    for (int oo = 0; oo < OCB / 2; oo++) wv[oo] = wp[oo];
                    #pragma unroll
                    for (int s = 0; s < 4; s++) {
                        float xv = xs[ci][tyy + s * 8 + ky][txx + kx];
                        u64 xv2 = pk2(xv, xv);
                        #pragma unroll
                        for (int oo = 0; oo < OCB / 2; oo++)
                            fma2(acc2[s][oo], xv2, wv[oo]);
                    }
                }
        }
        __syncthreads();
    }

    if (kind < 2) {
        float* outg = (kind == 0) ? g_qT : g_kT;
        float sc    = (kind == 0) ? 0.125f : 1.0f;
        #pragma unroll
        for (int s = 0; s < 4; s++) {
            float vals[OCB];
            #pragma unroll
            for (int oo = 0; oo < OCB / 2; oo++) {
                float2 f = upk2(acc2[s][oo]);
                vals[2 * oo]     = tf32r((f.x + bias[o0 + 2 * oo])     * sc);
                vals[2 * oo + 1] = tf32r((f.y + bias[o0 + 2 * oo + 1]) * sc);
            }
            int hw = (y0 + tyy + s * 8) * WW + x0 + txx;
            float* dst = outg + ((size_t)b * HWSZ + hw) * CQKD + o0;
            #pragma unroll
            for (int q4 = 0; q4 < 4; q4++)
                *(float4*)(dst + 4 * q4) = *(float4*)(vals + 4 * q4);
        }
    } else {
        #pragma unroll
        for (int oo = 0; oo < OCB / 2; oo++) {
            float b0 = bias[o0 + 2 * oo];
            float b1 = bias[o0 + 2 * oo + 1];
            #pragma unroll
            for (int s = 0; s < 4; s++) {
                float2 f = upk2(acc2[s][oo]);
                int gy = y0 + tyy + s * 8;
                size_t base = ((size_t)b * CHN + o0) * HWSZ + (size_t)gy * WW + x0 + txx;
                g_v[base + (size_t)(2 * oo)     * HWSZ] = tf32r(f.x + b0);
                g_v[base + (size_t)(2 * oo + 1) * HWSZ] = tf32r(f.y + b1);
            }
        }
    }
}

// ---------------------------------------------------------------------------
// K1: S = Q^T K via mma.sync tf32. CTA = 128(i) x 128(j), k = 64.
// 8 warps as 4(m) x 2(n); warp tile 32x64 = 2 mtiles x 8 ntiles of m16n8k8.
// grid (32 j, 32 i, 4 b), 256 thr, dyn smem 69632.
// ---------------------------------------------------------------------------
__global__ __launch_bounds__(256)
void qk_gemm()
{
    extern __shared__ float sm[];
    float* qs = sm;              // [128][68]
    float* ks = sm + 128 * 68;   // [128][68]

    const int t    = threadIdx.x;
    const int w    = t >> 5;
    const int lane = t & 31;
    const int g    = lane >> 2;
    const int tq   = lane & 3;
    const int j0 = blockIdx.x * 128;
    const int i0 = blockIdx.y * 128;
    const int b  = blockIdx.z;

    const float* qp = g_qT + ((size_t)b * HWSZ + i0) * CQKD;
    const float* kp = g_kT + ((size_t)b * HWSZ + j0) * CQKD;

    #pragma unroll
    for (int p = 0; p < 8; p++) {
        int fi = t + p * 256;
        int row = fi >> 4, c4 = fi & 15;
        *(float4*)(qs + row * 68 + c4 * 4) = *(const float4*)(qp + (size_t)row * CQKD + 4 * c4);
        *(float4*)(ks + row * 68 + c4 * 4) = *(const float4*)(kp + (size_t)row * CQKD + 4 * c4);
    }
    __syncthreads();

    const int wm = w >> 1;   // 0..3 -> rows wm*32
    const int wn = w & 1;    // 0..1 -> cols wn*64

    float acc[2][8][4];
    #pragma unroll
    for (int mt = 0; mt < 2; mt++)
        #pragma unroll
        for (int nt = 0; nt < 8; nt++)
            #pragma unroll
            for (int e = 0; e < 4; e++) acc[mt][nt][e] = 0.f;

    #pragma unroll
    for (int kst = 0; kst < 8; kst++) {
        int k0 = kst * 8;
        uint32_t af[2][4];
        #pragma unroll
        for (int mt = 0; mt < 2; mt++) {
            int r0 = wm * 32 + mt * 16;
            af[mt][0] = __float_as_uint(qs[(r0 + g)     * 68 + k0 + tq]);
            af[mt][1] = __float_as_uint(qs[(r0 + g + 8) * 68 + k0 + tq]);
            af[mt][2] = __float_as_uint(qs[(r0 + g)     * 68 + k0 + tq + 4]);
            af[mt][3] = __float_as_uint(qs[(r0 + g + 8) * 68 + k0 + tq + 4]);
        }
        #pragma unroll
        for (int nt = 0; nt < 8; nt++) {
            int c0 = wn * 64 + nt * 8;
            uint32_t b0 = __float_as_uint(ks[(c0 + g) * 68 + k0 + tq]);
            uint32_t b1 = __float_as_uint(ks[(c0 + g) * 68 + k0 + tq + 4]);
            mma8(acc[0][nt], af[0], b0, b1);
            mma8(acc[1][nt], af[1], b0, b1);
        }
    }
    __syncthreads();

    // stage through smem for coalesced S writes
    float* stage = sm;   // [128][132]
    #pragma unroll
    for (int mt = 0; mt < 2; mt++) {
        int r0 = wm * 32 + mt * 16;
        #pragma unroll
        for (int nt = 0; nt < 8; nt++) {
            int c0 = wn * 64 + nt * 8 + 2 * tq;
            stage[(r0 + g)     * 132 + c0]     = acc[mt][nt][0];
            stage[(r0 + g)     * 132 + c0 + 1] = acc[mt][nt][1];
            stage[(r0 + g + 8) * 132 + c0]     = acc[mt][nt][2];
            stage[(r0 + g + 8) * 132 + c0 + 1] = acc[mt][nt][3];
        }
    }
    __syncthreads();

    float* sp = g_s + ((size_t)b * HWSZ + i0) * HWSZ + j0;
    #pragma unroll
    for (int p = 0; p < 16; p++) {
        int fi = t + p * 256;
        int row = fi >> 5, q4 = fi & 31;
        *(float4*)(sp + (size_t)row * HWSZ + 4 * q4) =
            *(const float4*)(stage + row * 132 + 4 * q4);
    }
}

// ---------------------------------------------------------------------------
// K2: in-place row softmax over g_s; result rounded to tf32.
// ---------------------------------------------------------------------------
__global__ __launch_bounds__(256)
void softmax_rows()
{
    __shared__ float red[8];
    const int t = threadIdx.x;
    const int w = t >> 5, lane = t & 31;
    float* row = g_s + (size_t)blockIdx.x * HWSZ;

    float x[16];
    #pragma unroll
    for (int p = 0; p < 4; p++) {
        float4 v = *(const float4*)(row + 4 * (t + 256 * p));
        x[4 * p] = v.x; x[4 * p + 1] = v.y; x[4 * p + 2] = v.z; x[4 * p + 3] = v.w;
    }
    float m = x[0];
    #pragma unroll
    for (int i = 1; i < 16; i++) m = fmaxf(m, x[i]);
    #pragma unroll
    for (int off = 16; off; off >>= 1) m = fmaxf(m, __shfl_xor_sync(~0u, m, off));
    if (lane == 0) red[w] = m;
    __syncthreads();
    m = red[0];
    #pragma unroll
    for (int i = 1; i < 8; i++) m = fmaxf(m, red[i]);
    __syncthreads();

    float s = 0.f;
    #pragma unroll
    for (int i = 0; i < 16; i++) { x[i] = __expf(x[i] - m); s += x[i]; }
    #pragma unroll
    for (int off = 16; off; off >>= 1) s += __shfl_xor_sync(~0u, s, off);
    if (lane == 0) red[w] = s;
    __syncthreads();
    s = red[0];
    #pragma unroll
    for (int i = 1; i < 8; i++) s += red[i];
    float inv = 1.f / s;

    #pragma unroll
    for (int i = 0; i < 16; i++) x[i] = tf32r(x[i] * inv);
    #pragma unroll
    for (int p = 0; p < 4; p++)
        *(float4*)(row + 4 * (t + 256 * p)) =
            make_float4(x[4 * p], x[4 * p + 1], x[4 * p + 2], x[4 * p + 3]);
}

// ---------------------------------------------------------------------------
// K3: out[b][c][i] = sum_j P[i][j] V[c][j] via mma.sync tf32.
// CTA = 64(i) x 256(c); j streamed in 32-chunks, double-buffered cp.async.
// 8 warps as 4(m) x 2(n); warp tile 16 x 128 = 16 ntiles.
// grid (64, 4), 256 thr, dyn smem 92160.
// Buffers: buf k -> P [64][36] @ k*11520 floats, V [256][36] @ k*11520+2304.
// ---------------------------------------------------------------------------
__global__ __launch_bounds__(256)
void av_gemm(float* __restrict__ out)
{
    extern __shared__ float sm[];
    const uint32_t sb = smem_u32(sm);

    const int t    = threadIdx.x;
    const int w    = t >> 5;
    const int lane = t & 31;
    const int g    = lane >> 2;
    const int tq   = lane & 3;
    const int i0 = blockIdx.x * 64;
    const int b  = blockIdx.y;

    const float* Pb = g_s + ((size_t)b * HWSZ + i0) * HWSZ;
    const float* Vb = g_v + (size_t)b * CHN * HWSZ;

    const int wm = w >> 1;   // 0..3 -> rows wm*16
    const int wn = w & 1;    // 0..1 -> cols wn*128

    float acc[16][4];
    #pragma unroll
    for (int nt = 0; nt < 16; nt++)
        #pragma unroll
        for (int e = 0; e < 4; e++) acc[nt][e] = 0.f;

    // chunk loader: P 64x32, V 256x32 into buffer buf
    auto load_chunk = [&](int it, int buf) {
        uint32_t pb = sb + (uint32_t)(buf * 11520) * 4;
        uint32_t vb = pb + 2304 * 4;
        #pragma unroll
        for (int p = 0; p < 2; p++) {
            int fi = t + p * 256;
            int row = fi >> 3, c4 = fi & 7;
            cpa16(pb + (row * 36 + c4 * 4) * 4, Pb + (size_t)row * HWSZ + it * 32 + 4 * c4);
        }
        #pragma unroll
        for (int p = 0; p < 8; p++) {
            int fi = t + p * 256;
            int row = fi >> 3, c4 = fi & 7;
            cpa16(vb + (row * 36 + c4 * 4) * 4, Vb + (size_t)row * HWSZ + it * 32 + 4 * c4);
        }
        asm volatile("cp.async.commit_group;" ::: "memory");
    };

    load_chunk(0, 0);

    for (int it = 0; it < 128; it++) {
        const int buf = it & 1;
        if (it + 1 < 128) {
            load_chunk(it + 1, buf ^ 1);
            asm volatile("cp.async.wait_group 1;" ::: "memory");
        } else {
            asm volatile("cp.async.wait_group 0;" ::: "memory");
        }
        __syncthreads();

        const float* Ps = sm + buf * 11520;          // [64][36]
        const float* Vs = Ps + 2304;                 // [256][36]

        #pragma unroll
        for (int kst = 0; kst < 4; kst++) {
            int k0 = kst * 8;
            uint32_t af[4];
            int r0 = wm * 16;
            af[0] = __float_as_uint(Ps[(r0 + g)     * 36 + k0 + tq]);
            af[1] = __float_as_uint(Ps[(r0 + g + 8) * 36 + k0 + tq]);
            af[2] = __float_as_uint(Ps[(r0 + g)     * 36 + k0 + tq + 4]);
            af[3] = __float_as_uint(Ps[(r0 + g + 8) * 36 + k0 + tq + 4]);
            #pragma unroll
            for (int nt = 0; nt < 16; nt++) {
                int c0 = wn * 128 + nt * 8;
                uint32_t b0 = __float_as_uint(Vs[(c0 + g) * 36 + k0 + tq]);
                uint32_t b1 = __float_as_uint(Vs[(c0 + g) * 36 + k0 + tq + 4]);
                mma8(acc[nt], af, b0, b1);
            }
        }
        __syncthreads();
    }

    // epilogue: transpose through smem -> coalesced [c][i] stores
    float* stg = sm;   // [256][68]
    #pragma unroll
    for (int nt = 0; nt < 16; nt++) {
        int c0 = wn * 128 + nt * 8 + 2 * tq;
        int il = wm * 16;
        stg[c0       * 68 + il + g]     = acc[nt][0];
        stg[(c0 + 1) * 68 + il + g]     = acc[nt][1];
        stg[c0       * 68 + il + g + 8] = acc[nt][2];
        stg[(c0 + 1) * 68 + il + g + 8] = acc[nt][3];
    }
    __syncthreads();
    #pragma unroll
    for (int p = 0; p < 16; p++) {
        int fi = t + p * 256;
        int row = fi >> 4, q4 = fi & 15;
        *(float4*)(out + ((size_t)b * CHN + row) * HWSZ + i0 + 4 * q4) =
            *(const float4*)(stg + row * 68 + 4 * q4);
    }
}

// ---------------------------------------------------------------------------

static constexpr int QK_SMEM = 128 * 68 * 4 * 2;            // 69632
static constexpr int AV_SMEM = 2 * (64 * 36 + 256 * 36) * 4; // 92160

extern "C" void kernel_launch(void* const* d_in, const int* in_sizes, int n_in,
                              void* d_out, int out_size)
{
    const float* x   = (const float*)d_in[0];
    const float* q_w = (const float*)d_in[1];
    const float* q_b = (const float*)d_in[2];
    const float* k_w = (const float*)d_in[3];
    const float* k_b = (const float*)d_in[4];
    const float* v_w = (const float*)d_in[5];
    const float* v_b = (const float*)d_in[6];
    float* out = (float*)d_out;

    cudaFuncSetAttribute(qk_gemm, cudaFuncAttributeMaxDynamicSharedMemorySize, QK_SMEM);
    cudaFuncSetAttribute(av_gemm, cudaFuncAttributeMaxDynamicSharedMemorySize, AV_SMEM);

    conv3x3_all<<<dim3(2, 2, BATCH * 24), 256>>>(x, q_w, q_b, k_w, k_b, v_w, v_b);
    qk_gemm<<<dim3(HWSZ / 128, HWSZ / 128, BATCH), 256, QK_SMEM>>>();
    softmax_rows<<<BATCH * HWSZ, 256>>>();
    av_gemm<<<dim3(HWSZ / 64, BATCH), 256, AV_SMEM>>>(out);
}

// round 8
// speedup vs baseline: 9.7952x; 2.1693x over previous
#include <cuda_runtime.h>
#include <cstdint>

#define BATCH 4
#define CHN   256
#define CQKD  64
#define HH    64
#define WW    64
#define HWSZ  4096

// tf32-rounded copies of inputs  (16B-aligned)
__device__ __align__(16) float g_xr[BATCH * CHN * HWSZ];
__device__ __align__(16) float g_wr[(64 + 64 + 256) * CHN * 9];
// conv outputs (tf32-rounded fp32)
__device__ __align__(16) float g_qT[BATCH * HWSZ * CQKD];   // [b][hw][d], pre-scaled
__device__ __align__(16) float g_kT[BATCH * HWSZ * CQKD];   // [b][hw][d]
__device__ __align__(16) float g_v [BATCH * CHN  * HWSZ];   // [b][c][hw]
// attention matrix scratch (logits, then tf32 probs in-place)
__device__ __align__(16) float g_s [(size_t)BATCH * HWSZ * HWSZ];

typedef unsigned long long u64;

// ---------------- helpers ----------------
__device__ __forceinline__ float tf32r(float x) {
    uint32_t b; asm("cvt.rna.tf32.f32 %0, %1;" : "=r"(b) : "f"(x));
    return __uint_as_float(b);
}
__device__ __forceinline__ void mma8(float* c, const uint32_t* a,
                                     uint32_t b0, uint32_t b1) {
    asm volatile("mma.sync.aligned.m16n8k8.row.col.f32.tf32.tf32.f32 "
        "{%0,%1,%2,%3}, {%4,%5,%6,%7}, {%8,%9}, {%0,%1,%2,%3};"
        : "+f"(c[0]), "+f"(c[1]), "+f"(c[2]), "+f"(c[3])
        : "r"(a[0]), "r"(a[1]), "r"(a[2]), "r"(a[3]), "r"(b0), "r"(b1));
}
__device__ __forceinline__ void cpa16(uint32_t saddr, const float* g) {
    asm volatile("cp.async.cg.shared.global [%0], [%1], 16;"
                 :: "r"(saddr), "l"(g) : "memory");
}
__device__ __forceinline__ uint32_t smem_u32(const void* p) {
    return (uint32_t)__cvta_generic_to_shared((void*)p);
}

// ---------------------------------------------------------------------------
// K0: round x and weights to tf32 (rna) once.
// ---------------------------------------------------------------------------
__global__ __launch_bounds__(256)
void round_inputs(const float* __restrict__ x,  const float* __restrict__ qw,
                  const float* __restrict__ kw, const float* __restrict__ vw)
{
    const int tid = blockIdx.x * 256 + threadIdx.x;
    const int stride = gridDim.x * 256;
    const int NX = BATCH * CHN * HWSZ;
    const int WQ = 64 * CHN * 9;
    for (int i = tid; i < NX; i += stride) g_xr[i] = tf32r(x[i]);
    for (int i = tid; i < WQ; i += stride) g_wr[i] = tf32r(qw[i]);
    for (int i = tid; i < WQ; i += stride) g_wr[WQ + i] = tf32r(kw[i]);
    for (int i = tid; i < 4 * WQ; i += stride) g_wr[2 * WQ + i] = tf32r(vw[i]);
}

// ---------------------------------------------------------------------------
// K1: 3x3 conv as implicit GEMM on tensor cores (tf32 mma.sync).
// CTA: 64 output channels x 256 spatial (4 full image rows). k = 2304,
// processed as 32 ci-chunks of 8 x 9 taps. Double-buffered cp.async.
// Out-of-image rows & halo columns are pre-zeroed once; prefetch only
// writes valid rows. Out-of-range x-coords clamp to zero slot 64.
// 8 warps = 2(m) x 4(n); warp tile 32(o) x 64(n), k=8 per mma.
// grid (16 spatial tiles, 24 = b*6+og), 256 thr.
// ---------------------------------------------------------------------------
constexpr int CXS  = 68;                 // x tile row stride (64 data + 4 zero)
constexpr int XSF  = 8 * 6 * CXS;        // 3264 floats
constexpr int CWS  = 76;                 // w row stride (72 used)
constexpr int WSF  = 64 * CWS;           // 4864 floats
constexpr int CBUF = XSF + WSF;          // 8128 floats per buffer

__global__ __launch_bounds__(256)
void conv3x3_tc(const float* __restrict__ qb, const float* __restrict__ kb,
                const float* __restrict__ vb)
{
    extern __shared__ float sm[];
    const uint32_t sb = smem_u32(sm);

    const int t = threadIdx.x;
    const int w = t >> 5, lane = t & 31, g = lane >> 2, tq = lane & 3;
    const int y0  = blockIdx.x * 4;        // 4 image rows per CTA
    const int hw0 = y0 * WW;
    const int zz  = blockIdx.y;
    const int b   = zz / 6, og = zz % 6;

    const int WQ = 64 * CHN * 9;
    const float* wgt; const float* bias; int o0, kind;
    if (og == 0)      { wgt = g_wr;          bias = qb; o0 = 0;             kind = 0; }
    else if (og == 1) { wgt = g_wr + WQ;     bias = kb; o0 = 0;             kind = 1; }
    else              { wgt = g_wr + 2 * WQ; bias = vb; o0 = (og - 2) * 64; kind = 2; }

    const float* xb = g_xr + (size_t)b * CHN * HWSZ;
    const int wm = w >> 2, wn = w & 3;

    // pre-zero halo columns (64..67) and out-of-image rows, both buffers
    for (int idx = t; idx < 2 * XSF; idx += 256) {
        int bf = idx / XSF, r = idx % XSF;
        int ci = r / (6 * CXS), rr = r % (6 * CXS);
        int row = rr / CXS, cc = rr % CXS;
        int gy = y0 - 1 + row;
        if (cc >= 64 || (unsigned)gy >= (unsigned)HH)
            sm[bf * CBUF + ci * (6 * CXS) + row * CXS + cc] = 0.f;
    }
    __syncthreads();

    auto prefetch = [&](int c0, int buf) {
        uint32_t xd = sb + (uint32_t)(buf * CBUF) * 4;
        uint32_t wd = xd + (uint32_t)XSF * 4;
        #pragma unroll
        for (int p = 0; p < 3; p++) {                 // 768 = 8ci*6row*16
            int idx = t + p * 256;
            int ci = idx / 96, r = idx % 96;
            int row = r >> 4, q4 = r & 15;
            int gy = y0 - 1 + row;
            if ((unsigned)gy < (unsigned)HH) {
                const float* src = xb + (size_t)(c0 + ci) * HWSZ + gy * WW + q4 * 4;
                uint32_t dst = xd + (uint32_t)(ci * (6 * CXS) + row * CXS + q4 * 4) * 4;
                cpa16(dst, src);
            }
        }
        #pragma unroll
        for (int p = 0; p < 5; p++) {                 // 1152 = 64o * 18
            int idx = t + p * 256;
            if (idx < 1152) {
                int o = idx / 18, q = idx % 18;
                const float* src = wgt + (size_t)(o0 + o) * (CHN * 9) + c0 * 9 + q * 4;
                uint32_t dst = wd + (uint32_t)(o * CWS + q * 4) * 4;
                cpa16(dst, src);
            }
        }
        asm volatile("cp.async.commit_group;" ::: "memory");
    };

    float acc[2][8][4];
    #pragma unroll
    for (int mt = 0; mt < 2; mt++)
        #pragma unroll
        for (int nt = 0; nt < 8; nt++)
            #pragma unroll
            for (int e = 0; e < 4; e++) acc[mt][nt][e] = 0.f;

    prefetch(0, 0);
    for (int c = 0; c < 32; c++) {
        const int buf = c & 1;
        if (c + 1 < 32) {
            prefetch((c + 1) * 8, buf ^ 1);
            asm volatile("cp.async.wait_group 1;" ::: "memory");
        } else {
            asm volatile("cp.async.wait_group 0;" ::: "memory");
        }
        __syncthreads();

        const float* xsp = sm + buf * CBUF;
        const float* wsp = xsp + XSF;

        #pragma unroll
        for (int kk = 0; kk < 9; kk++) {
            const int ky = kk / 3, kx = kk - 3 * ky;
            uint32_t af[2][4];
            #pragma unroll
            for (int mt = 0; mt < 2; mt++) {
                const float* wb = wsp + (wm * 32 + mt * 16 + g) * CWS + tq * 9 + kk;
                af[mt][0] = __float_as_uint(wb[0]);
                af[mt][1] = __float_as_uint(wb[8 * CWS]);
                af[mt][2] = __float_as_uint(wb[36]);
                af[mt][3] = __float_as_uint(wb[8 * CWS + 36]);
            }
            #pragma unroll
            for (int nt = 0; nt < 8; nt++) {
                int n0 = wn * 64 + nt * 8;
                int ry = n0 >> 6, nx0 = n0 & 63;
                int icol = nx0 + g + kx - 1;               // -1..64
                int col  = ((unsigned)icol < 64u) ? icol : 64;  // 64 = zero slot
                const float* xp = xsp + (ry + ky) * CXS + col;
                uint32_t b0 = __float_as_uint(xp[tq * (6 * CXS)]);
                uint32_t b1 = __float_as_uint(xp[(tq + 4) * (6 * CXS)]);
                mma8(acc[0][nt], af[0], b0, b1);
                mma8(acc[1][nt], af[1], b0, b1);
            }
        }
        __syncthreads();
    }

    // epilogue: bias + (scale) + tf32 round, stage, coalesced store
    float* stg = sm;
    if (kind < 2) {
        float* outg = (kind == 0) ? g_qT : g_kT;
        float sc    = (kind == 0) ? 0.125f : 1.f;
        #pragma unroll
        for (int mt = 0; mt < 2; mt++) {
            int ob = wm * 32 + mt * 16 + g;
            float b0v = bias[o0 + ob], b1v = bias[o0 + ob + 8];
            #pragma unroll
            for (int nt = 0; nt < 8; nt++) {
                int n0 = wn * 64 + nt * 8 + 2 * tq;
                stg[n0       * 68 + ob]     = tf32r((acc[mt][nt][0] + b0v) * sc);
                stg[(n0 + 1) * 68 + ob]     = tf32r((acc[mt][nt][1] + b0v) * sc);
                stg[n0       * 68 + ob + 8] = tf32r((acc[mt][nt][2] + b1v) * sc);
                stg[(n0 + 1) * 68 + ob + 8] = tf32r((acc[mt][nt][3] + b1v) * sc);
            }
        }
        __syncthreads();
        float* dst = outg + ((size_t)b * HWSZ + hw0) * CQKD;
        #pragma unroll
        for (int p = 0; p < 16; p++) {
            int fi = t + p * 256;                 // 4096 f4 = 256 n x 16
            int n = fi >> 4, q4 = fi & 15;
            *(float4*)(dst + n * CQKD + 4 * q4) = *(const float4*)(stg + n * 68 + 4 * q4);
        }
    } else {
        #pragma unroll
        for (int mt = 0; mt < 2; mt++) {
            int ob = wm * 32 + mt * 16 + g;
            float b0v = bias[o0 + ob], b1v = bias[o0 + ob + 8];
            #pragma unroll
            for (int nt = 0; nt < 8; nt++) {
                int n0 = wn * 64 + nt * 8 + 2 * tq;
                stg[ob       * 260 + n0]     = tf32r(acc[mt][nt][0] + b0v);
                stg[ob       * 260 + n0 + 1] = tf32r(acc[mt][nt][1] + b0v);
                stg[(ob + 8) * 260 + n0]     = tf32r(acc[mt][nt][2] + b1v);
                stg[(ob + 8) * 260 + n0 + 1] = tf32r(acc[mt][nt][3] + b1v);
            }
        }
        __syncthreads();
        float* dst = g_v + ((size_t)b * CHN + o0) * HWSZ + hw0;
        #pragma unroll
        for (int p = 0; p < 16; p++) {
            int fi = t + p * 256;                 // 4096 f4 = 64 o x 64
            int o = fi >> 6, q4 = fi & 63;
            *(float4*)(dst + (size_t)o * HWSZ + 4 * q4) = *(const float4*)(stg + o * 260 + 4 * q4);
        }
    }
}

// ---------------------------------------------------------------------------
// K2: S = Q^T K via mma.sync tf32. CTA = 128(i) x 128(j), k = 64.
// ---------------------------------------------------------------------------
__global__ __launch_bounds__(256)
void qk_gemm()
{
    extern __shared__ float sm[];
    float* qs = sm;              // [128][68]
    float* ks = sm + 128 * 68;   // [128][68]

    const int t    = threadIdx.x;
    const int w    = t >> 5;
    const int lane = t & 31;
    const int g    = lane >> 2;
    const int tq   = lane & 3;
    const int j0 = blockIdx.x * 128;
    const int i0 = blockIdx.y * 128;
    const int b  = blockIdx.z;

    const float* qp = g_qT + ((size_t)b * HWSZ + i0) * CQKD;
    const float* kp = g_kT + ((size_t)b * HWSZ + j0) * CQKD;

    #pragma unroll
    for (int p = 0; p < 8; p++) {
        int fi = t + p * 256;
        int row = fi >> 4, c4 = fi & 15;
        *(float4*)(qs + row * 68 + c4 * 4) = *(const float4*)(qp + (size_t)row * CQKD + 4 * c4);
        *(float4*)(ks + row * 68 + c4 * 4) = *(const float4*)(kp + (size_t)row * CQKD + 4 * c4);
    }
    __syncthreads();

    const int wm = w >> 1;
    const int wn = w & 1;

    float acc[2][8][4];
    #pragma unroll
    for (int mt = 0; mt < 2; mt++)
        #pragma unroll
        for (int nt = 0; nt < 8; nt++)
            #pragma unroll
            for (int e = 0; e < 4; e++) acc[mt][nt][e] = 0.f;

    #pragma unroll
    for (int kst = 0; kst < 8; kst++) {
        int k0 = kst * 8;
        uint32_t af[2][4];
        #pragma unroll
        for (int mt = 0; mt < 2; mt++) {
            int r0 = wm * 32 + mt * 16;
            af[mt][0] = __float_as_uint(qs[(r0 + g)     * 68 + k0 + tq]);
            af[mt][1] = __float_as_uint(qs[(r0 + g + 8) * 68 + k0 + tq]);
            af[mt][2] = __float_as_uint(qs[(r0 + g)     * 68 + k0 + tq + 4]);
            af[mt][3] = __float_as_uint(qs[(r0 + g + 8) * 68 + k0 + tq + 4]);
        }
        #pragma unroll
        for (int nt = 0; nt < 8; nt++) {
            int c0 = wn * 64 + nt * 8;
            uint32_t b0 = __float_as_uint(ks[(c0 + g) * 68 + k0 + tq]);
            uint32_t b1 = __float_as_uint(ks[(c0 + g) * 68 + k0 + tq + 4]);
            mma8(acc[0][nt], af[0], b0, b1);
            mma8(acc[1][nt], af[1], b0, b1);
        }
    }
    __syncthreads();

    float* stage = sm;   // [128][132]
    #pragma unroll
    for (int mt = 0; mt < 2; mt++) {
        int r0 = wm * 32 + mt * 16;
        #pragma unroll
        for (int nt = 0; nt < 8; nt++) {
            int c0 = wn * 64 + nt * 8 + 2 * tq;
            stage[(r0 + g)     * 132 + c0]     = acc[mt][nt][0];
            stage[(r0 + g)     * 132 + c0 + 1] = acc[mt][nt][1];
            stage[(r0 + g + 8) * 132 + c0]     = acc[mt][nt][2];
            stage[(r0 + g + 8) * 132 + c0 + 1] = acc[mt][nt][3];
        }
    }
    __syncthreads();

    float* sp = g_s + ((size_t)b * HWSZ + i0) * HWSZ + j0;
    #pragma unroll
    for (int p = 0; p < 16; p++) {
        int fi = t + p * 256;
        int row = fi >> 5, q4 = fi & 31;
        *(float4*)(sp + (size_t)row * HWSZ + 4 * q4) =
            *(const float4*)(stage + row * 132 + 4 * q4);
    }
}

// ---------------------------------------------------------------------------
// K3: in-place row softmax over g_s; result rounded to tf32.
// ---------------------------------------------------------------------------
__global__ __launch_bounds__(256)
void softmax_rows()
{
    __shared__ float red[8];
    const int t = threadIdx.x;
    const int w = t >> 5, lane = t & 31;
    float* row = g_s + (size_t)blockIdx.x * HWSZ;

    float x[16];
    #pragma unroll
    for (int p = 0; p < 4; p++) {
        float4 v = *(const float4*)(row + 4 * (t + 256 * p));
        x[4 * p] = v.x; x[4 * p + 1] = v.y; x[4 * p + 2] = v.z; x[4 * p + 3] = v.w;
    }
    float m = x[0];
    #pragma unroll
    for (int i = 1; i < 16; i++) m = fmaxf(m, x[i]);
    #pragma unroll
    for (int off = 16; off; off >>= 1) m = fmaxf(m, __shfl_xor_sync(~0u, m, off));
    if (lane == 0) red[w] = m;
    __syncthreads();
    m = red[0];
    #pragma unroll
    for (int i = 1; i < 8; i++) m = fmaxf(m, red[i]);
    __syncthreads();

    float s = 0.f;
    #pragma unroll
    for (int i = 0; i < 16; i++) { x[i] = __expf(x[i] - m); s += x[i]; }
    #pragma unroll
    for (int off = 16; off; off >>= 1) s += __shfl_xor_sync(~0u, s, off);
    if (lane == 0) red[w] = s;
    __syncthreads();
    s = red[0];
    #pragma unroll
    for (int i = 1; i < 8; i++) s += red[i];
    float inv = 1.f / s;

    #pragma unroll
    for (int i = 0; i < 16; i++) x[i] = tf32r(x[i] * inv);
    #pragma unroll
    for (int p = 0; p < 4; p++)
        *(float4*)(row + 4 * (t + 256 * p)) =
            make_float4(x[4 * p], x[4 * p + 1], x[4 * p + 2], x[4 * p + 3]);
}

// ---------------------------------------------------------------------------
// K4: out[b][c][i] = sum_j P[i][j] V[c][j] via mma.sync tf32.
// CTA = 128(i) x 256(c); j streamed in 32-chunks, double-buffered cp.async.
// 8 warps = 4(m) x 2(n); warp tile 32(i) x 128(c).
// grid (32, 4), 256 thr.
// ---------------------------------------------------------------------------
constexpr int PBF  = 128 * 36;     // 4608
constexpr int VBF  = 256 * 36;     // 9216
constexpr int ABUF = PBF + VBF;    // 13824 floats per buffer

__global__ __launch_bounds__(256)
void av_gemm(float* __restrict__ out)
{
    extern __shared__ float sm[];
    const uint32_t sb = smem_u32(sm);

    const int t    = threadIdx.x;
    const int w    = t >> 5;
    const int lane = t & 31;
    const int g    = lane >> 2;
    const int tq   = lane & 3;
    const int i0 = blockIdx.x * 128;
    const int b  = blockIdx.y;

    const float* Pb = g_s + ((size_t)b * HWSZ + i0) * HWSZ;
    const float* Vb = g_v + (size_t)b * CHN * HWSZ;

    const int wm = w >> 1;   // 0..3 -> rows wm*32
    const int wn = w & 1;    // 0..1 -> cols wn*128

    float acc[2][16][4];
    #pragma unroll
    for (int mt = 0; mt < 2; mt++)
        #pragma unroll
        for (int nt = 0; nt < 16; nt++)
            #pragma unroll
            for (int e = 0; e < 4; e++) acc[mt][nt][e] = 0.f;

    auto load_chunk = [&](int it, int buf) {
        uint32_t pb = sb + (uint32_t)(buf * ABUF) * 4;
        uint32_t vbp = pb + (uint32_t)PBF * 4;
        #pragma unroll
        for (int p = 0; p < 4; p++) {                 // P: 128 x 32
            int fi = t + p * 256;
            int row = fi >> 3, c4 = fi & 7;
            cpa16(pb + (uint32_t)(row * 36 + c4 * 4) * 4,
                  Pb + (size_t)row * HWSZ + it * 32 + 4 * c4);
        }
        #pragma unroll
        for (int p = 0; p < 8; p++) {                 // V: 256 x 32
            int fi = t + p * 256;
            int row = fi >> 3, c4 = fi & 7;
            cpa16(vbp + (uint32_t)(row * 36 + c4 * 4) * 4,
                  Vb + (size_t)row * HWSZ + it * 32 + 4 * c4);
        }
        asm volatile("cp.async.commit_group;" ::: "memory");
    };

    load_chunk(0, 0);
    for (int it = 0; it < 128; it++) {
        const int buf = it & 1;
        if (it + 1 < 128) {
            load_chunk(it + 1, buf ^ 1);
            asm volatile("cp.async.wait_group 1;" ::: "memory");
        } else {
            asm volatile("cp.async.wait_group 0;" ::: "memory");
        }
        __syncthreads();

        const float* Ps = sm + buf * ABUF;            // [128][36]
        const float* Vs = Ps + PBF;                   // [256][36]

        #pragma unroll
        for (int kst = 0; kst < 4; kst++) {
            int k0 = kst * 8;
            uint32_t af[2][4];
            #pragma unroll
            for (int mt = 0; mt < 2; mt++) {
                int r0 = wm * 32 + mt * 16;
                af[mt][0] = __float_as_uint(Ps[(r0 + g)     * 36 + k0 + tq]);
                af[mt][1] = __float_as_uint(Ps[(r0 + g + 8) * 36 + k0 + tq]);
                af[mt][2] = __float_as_uint(Ps[(r0 + g)     * 36 + k0 + tq + 4]);
                af[mt][3] = __float_as_uint(Ps[(r0 + g + 8) * 36 + k0 + tq + 4]);
            }
            #pragma unroll
            for (int nt = 0; nt < 16; nt++) {
                int c0 = wn * 128 + nt * 8;
                uint32_t b0 = __float_as_uint(Vs[(c0 + g) * 36 + k0 + tq]);
                uint32_t b1 = __float_as_uint(Vs[(c0 + g) * 36 + k0 + tq + 4]);
                mma8(acc[0][nt], af[0], b0, b1);
                mma8(acc[1][nt], af[1], b0, b1);
            }
        }
        __syncthreads();
    }

    // epilogue: two halves of channels staged [128][132], coalesced stores
    float* stg = sm;
    for (int h = 0; h < 2; h++) {
        __syncthreads();
        if (wn == h) {
            #pragma unroll
            for (int mt = 0; mt < 2; mt++) {
                int il = wm * 32 + mt * 16;
                #pragma unroll
                for (int nt = 0; nt < 16; nt++) {
                    int cl = nt * 8 + 2 * tq;
                    stg[cl       * 132 + il + g]     = acc[mt][nt][0];
                    stg[(cl + 1) * 132 + il + g]     = acc[mt][nt][1];
                    stg[cl       * 132 + il + g + 8] = acc[mt][nt][2];
                    stg[(cl + 1) * 132 + il + g + 8] = acc[mt][nt][3];
                }
            }
        }
        __syncthreads();
        float* dst = out + ((size_t)b * CHN + h * 128) * HWSZ + i0;
        #pragma unroll
        for (int p = 0; p < 16; p++) {
            int fi = t + p * 256;                 // 4096 f4 = 128 c x 32
            int c = fi >> 5, q4 = fi & 31;
            *(float4*)(dst + (size_t)c * HWSZ + 4 * q4) =
                *(const float4*)(stg + c * 132 + 4 * q4);
        }
    }
}

// ---------------------------------------------------------------------------

static constexpr int CONV_SMEM = 256 * 68 * 4;               // 69632 (stage dominates)
static constexpr int QK_SMEM   = 128 * 68 * 4 * 2;           // 69632
static constexpr int AV_SMEM   = 2 * ABUF * 4;               // 110592

extern "C" void kernel_launch(void* const* d_in, const int* in_sizes, int n_in,
                              void* d_out, int out_size)
{
    const float* x   = (const float*)d_in[0];
    const float* q_w = (const float*)d_in[1];
    const float* q_b = (const float*)d_in[2];
    const float* k_w = (const float*)d_in[3];
    const float* k_b = (const float*)d_in[4];
    const float* v_w = (const float*)d_in[5];
    const float* v_b = (const float*)d_in[6];
    float* out = (float*)d_out;

    cudaFuncSetAttribute(conv3x3_tc, cudaFuncAttributeMaxDynamicSharedMemorySize, CONV_SMEM);
    cudaFuncSetAttribute(qk_gemm,    cudaFuncAttributeMaxDynamicSharedMemorySize, QK_SMEM);
    cudaFuncSetAttribute(av_gemm,    cudaFuncAttributeMaxDynamicSharedMemorySize, AV_SMEM);

    round_inputs<<<2048, 256>>>(x, q_w, k_w, v_w);
    conv3x3_tc<<<dim3(16, 24), 256, CONV_SMEM>>>(q_b, k_b, v_b);
    qk_gemm<<<dim3(HWSZ / 128, HWSZ / 128, BATCH), 256, QK_SMEM>>>();
    softmax_rows<<<BATCH * HWSZ, 256>>>();
    av_gemm<<<dim3(HWSZ / 128, BATCH), 256, AV_SMEM>>>(out);
}

// round 9
// speedup vs baseline: 18.0555x; 1.8433x over previous
#include <cuda_runtime.h>
#include <cuda_fp16.h>
#include <cstdint>

#define BATCH 4
#define CHN   256
#define CQKD  64
#define HH    64
#define WW    64
#define HWSZ  4096

// fp16 tensors (fp32 accumulate everywhere)
__device__ __align__(16) __half g_xh[BATCH * HWSZ * CHN];          // [b][hw][ci]
__device__ __align__(16) __half g_wh[384 * 9 * CHN];               // [o][tap][ci], q|k|v
__device__ __align__(16) __half g_qh[BATCH * HWSZ * CQKD];         // [b][hw][d], pre-scaled
__device__ __align__(16) __half g_kh[BATCH * HWSZ * CQKD];         // [b][hw][d]
__device__ __align__(16) __half g_vh[BATCH * CHN * HWSZ];          // [b][c][hw]
__device__ __align__(16) __half g_sh[(size_t)BATCH * HWSZ * HWSZ]; // logits -> probs

// ---------------- helpers ----------------
__device__ __forceinline__ void mma16(float* c, const uint32_t* a,
                                      uint32_t b0, uint32_t b1) {
    asm volatile("mma.sync.aligned.m16n8k16.row.col.f32.f16.f16.f32 "
        "{%0,%1,%2,%3}, {%4,%5,%6,%7}, {%8,%9}, {%0,%1,%2,%3};"
        : "+f"(c[0]), "+f"(c[1]), "+f"(c[2]), "+f"(c[3])
        : "r"(a[0]), "r"(a[1]), "r"(a[2]), "r"(a[3]), "r"(b0), "r"(b1));
}
__device__ __forceinline__ void cpa16(uint32_t saddr, const void* g) {
    asm volatile("cp.async.cg.shared.global [%0], [%1], 16;"
                 :: "r"(saddr), "l"(g) : "memory");
}
__device__ __forceinline__ uint32_t smem_u32(const void* p) {
    return (uint32_t)__cvta_generic_to_shared((void*)p);
}
__device__ __forceinline__ uint32_t ldsm_u32(const __half* p) {
    return *(const uint32_t*)p;
}

// ---------------------------------------------------------------------------
// K0a: transpose+convert x: [b][ci][hw] fp32 -> [b][hw][ci] fp16.
// block handles 64 ci x 64 hw; grid 4*4*64 = 1024.
// ---------------------------------------------------------------------------
__global__ __launch_bounds__(256)
void cvt_x(const float* __restrict__ x)
{
    __shared__ __half ts[64][72];
    const int t = threadIdx.x;
    const int blk = blockIdx.x;
    const int b = blk >> 8, r = blk & 255;
    const int ci0 = (r >> 6) * 64, hw0 = (r & 63) * 64;

    #pragma unroll
    for (int p = 0; p < 4; p++) {
        int idx = t + p * 256;
        int ci = idx >> 4, hq = idx & 15;
        float4 v = *(const float4*)(x + ((size_t)(b * CHN + ci0 + ci)) * HWSZ + hw0 + 4 * hq);
        ts[ci][4 * hq + 0] = __float2half_rn(v.x);
        ts[ci][4 * hq + 1] = __float2half_rn(v.y);
        ts[ci][4 * hq + 2] = __float2half_rn(v.z);
        ts[ci][4 * hq + 3] = __float2half_rn(v.w);
    }
    __syncthreads();
    #pragma unroll
    for (int p = 0; p < 2; p++) {
        int idx = t + p * 256;
        int hw = idx >> 3, c8 = idx & 7;
        union { __half h[8]; uint4 u; } pk;
        #pragma unroll
        for (int e = 0; e < 8; e++) pk.h[e] = ts[c8 * 8 + e][hw];
        *(uint4*)(g_xh + ((size_t)(b * HWSZ + hw0 + hw)) * CHN + ci0 + c8 * 8) = pk.u;
    }
}

// ---------------------------------------------------------------------------
// K0b: weights [o][ci][9] fp32 -> [o][tap][ci] fp16. grid 384 (one o per block).
// ---------------------------------------------------------------------------
__global__ __launch_bounds__(256)
void cvt_w(const float* __restrict__ qw, const float* __restrict__ kw,
           const float* __restrict__ vw)
{
    const int o = blockIdx.x, t = threadIdx.x;
    const float* w; int ol;
    if (o < 64)       { w = qw; ol = o; }
    else if (o < 128) { w = kw; ol = o - 64; }
    else              { w = vw; ol = o - 128; }
    #pragma unroll
    for (int tap = 0; tap < 9; tap++)
        g_wh[((size_t)o * 9 + tap) * CHN + t] =
            __float2half_rn(w[((size_t)ol * CHN + t) * 9 + tap]);
}

// ---------------------------------------------------------------------------
// K1: 3x3 conv as implicit GEMM, fp16 HMMA (m16n8k16). CTA: 64 oc x 256 spatial.
// 16 ci-chunks of 16 x 9 taps. x smem [6 rows][68 cols][24 ci-pad] fp16;
// w smem [64 o][9 tap][24 ci-pad]. Double-buffered cp.async.
// 8 warps = 2(m) x 4(n). grid (16, 24), 256 thr.
// ---------------------------------------------------------------------------
constexpr int CIP    = 24;                  // padded ci stride (fp16)
constexpr int XSF16  = 6 * 68 * CIP;        // 9792 halves
constexpr int WSF16  = 64 * 9 * CIP;        // 13824 halves
constexpr int CBUF16 = XSF16 + WSF16;       // 23616 halves = 47232 B

__global__ __launch_bounds__(256)
void conv3x3_tc(const float* __restrict__ qb, const float* __restrict__ kb,
                const float* __restrict__ vb)
{
    extern __shared__ char smraw[];
    __half* sh = (__half*)smraw;
    const uint32_t sb = smem_u32(smraw);

    const int t = threadIdx.x;
    const int w = t >> 5, lane = t & 31, g = lane >> 2, tq = lane & 3;
    const int y0  = blockIdx.x * 4;
    const int hw0 = y0 * WW;
    const int zz  = blockIdx.y;
    const int b   = zz / 6, og = zz % 6;

    const float* bias; int wo0, o0l, kind;
    if (og == 0)      { bias = qb; wo0 = 0;                  o0l = 0;             kind = 0; }
    else if (og == 1) { bias = kb; wo0 = 64;                 o0l = 0;             kind = 1; }
    else              { bias = vb; wo0 = 128 + (og - 2) * 64; o0l = (og - 2) * 64; kind = 2; }

    const int wm = w >> 2, wn = w & 3;

    // zero halo cols (>=64) and out-of-image rows, both buffers (uint4 granularity)
    {
        const uint4 z = make_uint4(0, 0, 0, 0);
        for (int idx = t; idx < 2 * 6 * 68 * 2; idx += 256) {
            int buf = idx / 816, rcq = idx % 816;
            int row = rcq / 136, cc = rcq % 136;
            int col = cc >> 1, ci8 = cc & 1;
            int gy = y0 - 1 + row;
            if (col >= 64 || (unsigned)gy >= (unsigned)HH)
                *(uint4*)(sh + buf * CBUF16 + (row * 68 + col) * CIP + ci8 * 8) = z;
        }
    }
    __syncthreads();

    auto prefetch = [&](int c0, int buf) {
        uint32_t xd = sb + (uint32_t)(buf * CBUF16) * 2;
        uint32_t wd = xd + (uint32_t)XSF16 * 2;
        #pragma unroll
        for (int p = 0; p < 3; p++) {                   // x: 768 cps (6r*64c*2)
            int idx = t + p * 256;
            int ci8 = idx & 1, col = (idx >> 1) & 63, row = idx >> 7;
            int gy = y0 - 1 + row;
            if ((unsigned)gy < (unsigned)HH) {
                const __half* src = g_xh + ((size_t)(b * HWSZ + gy * WW + col)) * CHN + c0 + ci8 * 8;
                uint32_t dst = xd + (uint32_t)((row * 68 + col) * CIP + ci8 * 8) * 2;
                cpa16(dst, src);
            }
        }
        #pragma unroll
        for (int p = 0; p < 5; p++) {                   // w: 1152 cps (64o*9*2)
            int idx = t + p * 256;
            if (idx < 1152) {
                int ci8 = idx & 1, r = idx >> 1;
                int o = r / 9, kk = r % 9;
                const __half* src = g_wh + ((size_t)(wo0 + o) * 9 + kk) * CHN + c0 + ci8 * 8;
                uint32_t dst = wd + (uint32_t)((o * 9 + kk) * CIP + ci8 * 8) * 2;
                cpa16(dst, src);
            }
        }
        asm volatile("cp.async.commit_group;" ::: "memory");
    };

    float acc[2][8][4];
    #pragma unroll
    for (int mt = 0; mt < 2; mt++)
        #pragma unroll
        for (int nt = 0; nt < 8; nt++)
            #pragma unroll
            for (int e = 0; e < 4; e++) acc[mt][nt][e] = 0.f;

    prefetch(0, 0);
    for (int c = 0; c < 16; c++) {
        const int buf = c & 1;
        if (c + 1 < 16) {
            prefetch((c + 1) * 16, buf ^ 1);
            asm volatile("cp.async.wait_group 1;" ::: "memory");
        } else {
            asm volatile("cp.async.wait_group 0;" ::: "memory");
        }
        __syncthreads();

        const __half* xsp = sh + buf * CBUF16;
        const __half* wsp = xsp + XSF16;

        #pragma unroll
        for (int kk = 0; kk < 9; kk++) {
            const int ky = kk / 3, kx = kk - 3 * ky;
            uint32_t af[2][4];
            #pragma unroll
            for (int mt = 0; mt < 2; mt++) {
                const __half* wb = wsp + ((wm * 32 + mt * 16 + g) * 9 + kk) * CIP;
                af[mt][0] = ldsm_u32(wb + 2 * tq);
                af[mt][1] = ldsm_u32(wb + 8 * 9 * CIP + 2 * tq);
                af[mt][2] = ldsm_u32(wb + 2 * tq + 8);
                af[mt][3] = ldsm_u32(wb + 8 * 9 * CIP + 2 * tq + 8);
            }
            #pragma unroll
            for (int nt = 0; nt < 8; nt++) {
                int icol = nt * 8 + g + kx - 1;                 // -1..64
                int col  = ((unsigned)icol < 64u) ? icol : 64;   // 64 = zero slot
                const __half* xp = xsp + ((wn + ky) * 68 + col) * CIP;
                uint32_t b0 = ldsm_u32(xp + 2 * tq);
                uint32_t b1 = ldsm_u32(xp + 2 * tq + 8);
                mma16(acc[0][nt], af[0], b0, b1);
                mma16(acc[1][nt], af[1], b0, b1);
            }
        }
        __syncthreads();
    }

    // epilogue: bias (+scale), convert fp16, stage, coalesced store
    __half* stg = sh;
    if (kind < 2) {
        __half* outg = (kind == 0) ? g_qh : g_kh;
        const float sc = (kind == 0) ? 0.125f : 1.f;
        #pragma unroll
        for (int mt = 0; mt < 2; mt++) {
            int ob = wm * 32 + mt * 16 + g;
            float b0v = bias[ob], b1v = bias[ob + 8];
            #pragma unroll
            for (int nt = 0; nt < 8; nt++) {
                int n0 = wn * 64 + nt * 8 + 2 * tq;
                stg[n0 * 72 + ob]           = __float2half_rn((acc[mt][nt][0] + b0v) * sc);
                stg[(n0 + 1) * 72 + ob]     = __float2half_rn((acc[mt][nt][1] + b0v) * sc);
                stg[n0 * 72 + ob + 8]       = __float2half_rn((acc[mt][nt][2] + b1v) * sc);
                stg[(n0 + 1) * 72 + ob + 8] = __float2half_rn((acc[mt][nt][3] + b1v) * sc);
            }
        }
        __syncthreads();
        #pragma unroll
        for (int p = 0; p < 8; p++) {
            int idx = t + p * 256;               // 2048 = 256 n x 8 uint4
            int n = idx >> 3, q8 = idx & 7;
            *(uint4*)(outg + ((size_t)(b * HWSZ + hw0 + n)) * CQKD + q8 * 8) =
                *(const uint4*)(stg + n * 72 + q8 * 8);
        }
    } else {
        #pragma unroll
        for (int mt = 0; mt < 2; mt++) {
            int ob = wm * 32 + mt * 16 + g;
            float b0v = bias[o0l + ob], b1v = bias[o0l + ob + 8];
            #pragma unroll
            for (int nt = 0; nt < 8; nt++) {
                int n0 = wn * 64 + nt * 8 + 2 * tq;
                *(__half2*)(stg + ob * 264 + n0) =
                    __floats2half2_rn(acc[mt][nt][0] + b0v, acc[mt][nt][1] + b0v);
                *(__half2*)(stg + (ob + 8) * 264 + n0) =
                    __floats2half2_rn(acc[mt][nt][2] + b1v, acc[mt][nt][3] + b1v);
            }
        }
        __syncthreads();
        #pragma unroll
        for (int p = 0; p < 8; p++) {
            int idx = t + p * 256;               // 2048 = 64 o x 32 uint4
            int o = idx >> 5, q8 = idx & 31;
            *(uint4*)(g_vh + ((size_t)(b * CHN + o0l + o)) * HWSZ + hw0 + q8 * 8) =
                *(const uint4*)(stg + o * 264 + q8 * 8);
        }
    }
}

// ---------------------------------------------------------------------------
// K2: S = Q^T K, fp16 HMMA. CTA = 128(i) x 128(j), k = 64 (4 ksteps).
// smem [128][72] fp16 per operand; S written fp16 via [128][136] stage.
// ---------------------------------------------------------------------------
__global__ __launch_bounds__(256)
void qk_gemm()
{
    extern __shared__ char smraw[];
    __half* sh = (__half*)smraw;
    __half* qs = sh;
    __half* ks = sh + 128 * 72;

    const int t = threadIdx.x;
    const int w = t >> 5, lane = t & 31, g = lane >> 2, tq = lane & 3;
    const int j0 = blockIdx.x * 128;
    const int i0 = blockIdx.y * 128;
    const int b  = blockIdx.z;

    #pragma unroll
    for (int p = 0; p < 8; p++) {
        int idx = t + p * 256;                   // 2048 = 2 arr x 128 r x 8 u4
        int arr = idx >> 10, r2 = idx & 1023;
        int row = r2 >> 3, q8 = r2 & 7;
        const __half* src = (arr ? g_kh + ((size_t)(b * HWSZ + j0 + row)) * CQKD
                                 : g_qh + ((size_t)(b * HWSZ + i0 + row)) * CQKD) + q8 * 8;
        __half* dst = (arr ? ks : qs) + row * 72 + q8 * 8;
        *(uint4*)dst = *(const uint4*)src;
    }
    __syncthreads();

    const int wm = w >> 1, wn = w & 1;

    float acc[2][8][4];
    #pragma unroll
    for (int mt = 0; mt < 2; mt++)
        #pragma unroll
        for (int nt = 0; nt < 8; nt++)
            #pragma unroll
            for (int e = 0; e < 4; e++) acc[mt][nt][e] = 0.f;

    #pragma unroll
    for (int kst = 0; kst < 4; kst++) {
        int k0 = kst * 16;
        uint32_t af[2][4];
        #pragma unroll
        for (int mt = 0; mt < 2; mt++) {
            const __half* qp = qs + (wm * 32 + mt * 16 + g) * 72 + k0;
            af[mt][0] = ldsm_u32(qp + 2 * tq);
            af[mt][1] = ldsm_u32(qp + 8 * 72 + 2 * tq);
            af[mt][2] = ldsm_u32(qp + 2 * tq + 8);
            af[mt][3] = ldsm_u32(qp + 8 * 72 + 2 * tq + 8);
        }
        #pragma unroll
        for (int nt = 0; nt < 8; nt++) {
            const __half* kp = ks + (wn * 64 + nt * 8 + g) * 72 + k0;
            uint32_t b0 = ldsm_u32(kp + 2 * tq);
            uint32_t b1 = ldsm_u32(kp + 2 * tq + 8);
            mma16(acc[0][nt], af[0], b0, b1);
            mma16(acc[1][nt], af[1], b0, b1);
        }
    }
    __syncthreads();

    __half* stg = sh;    // [128][136]
    #pragma unroll
    for (int mt = 0; mt < 2; mt++) {
        int r0 = wm * 32 + mt * 16;
        #pragma unroll
        for (int nt = 0; nt < 8; nt++) {
            int cc = wn * 64 + nt * 8 + 2 * tq;
            *(__half2*)(stg + (r0 + g) * 136 + cc) =
                __floats2half2_rn(acc[mt][nt][0], acc[mt][nt][1]);
            *(__half2*)(stg + (r0 + g + 8) * 136 + cc) =
                __floats2half2_rn(acc[mt][nt][2], acc[mt][nt][3]);
        }
    }
    __syncthreads();
    #pragma unroll
    for (int p = 0; p < 8; p++) {
        int idx = t + p * 256;                   // 2048 = 128 r x 16 u4
        int row = idx >> 4, q8 = idx & 15;
        *(uint4*)(g_sh + ((size_t)(b * HWSZ + i0 + row)) * HWSZ + j0 + q8 * 8) =
            *(const uint4*)(stg + row * 136 + q8 * 8);
    }
}

// ---------------------------------------------------------------------------
// K3: in-place fp16 row softmax over g_sh (fp32 math).
// ---------------------------------------------------------------------------
__global__ __launch_bounds__(256)
void softmax_rows()
{
    __shared__ float red[8];
    const int t = threadIdx.x;
    const int w = t >> 5, lane = t & 31;
    __half* row = g_sh + (size_t)blockIdx.x * HWSZ;

    uint4 v[2];
    float x[16];
    #pragma unroll
    for (int p = 0; p < 2; p++) v[p] = ((const uint4*)row)[t + 256 * p];
    #pragma unroll
    for (int p = 0; p < 2; p++) {
        const uint32_t* u = (const uint32_t*)&v[p];
        #pragma unroll
        for (int q = 0; q < 4; q++) {
            float2 f = __half22float2(*(const __half2*)&u[q]);
            x[p * 8 + q * 2]     = f.x;
            x[p * 8 + q * 2 + 1] = f.y;
        }
    }

    float m = x[0];
    #pragma unroll
    for (int i = 1; i < 16; i++) m = fmaxf(m, x[i]);
    #pragma unroll
    for (int off = 16; off; off >>= 1) m = fmaxf(m, __shfl_xor_sync(~0u, m, off));
    if (lane == 0) red[w] = m;
    __syncthreads();
    m = red[0];
    #pragma unroll
    for (int i = 1; i < 8; i++) m = fmaxf(m, red[i]);
    __syncthreads();

    float s = 0.f;
    #pragma unroll
    for (int i = 0; i < 16; i++) { x[i] = __expf(x[i] - m); s += x[i]; }
    #pragma unroll
    for (int off = 16; off; off >>= 1) s += __shfl_xor_sync(~0u, s, off);
    if (lane == 0) red[w] = s;
    __syncthreads();
    s = red[0];
    #pragma unroll
    for (int i = 1; i < 8; i++) s += red[i];
    const float inv = 1.f / s;

    #pragma unroll
    for (int p = 0; p < 2; p++) {
        uint32_t* u = (uint32_t*)&v[p];
        #pragma unroll
        for (int q = 0; q < 4; q++) {
            __half2 hh = __floats2half2_rn(x[p * 8 + q * 2] * inv,
                                           x[p * 8 + q * 2 + 1] * inv);
            u[q] = *(const uint32_t*)&hh;
        }
        ((uint4*)row)[t + 256 * p] = v[p];
    }
}

// ---------------------------------------------------------------------------
// K4: out[b][c][i] = sum_j P[i][j] V[c][j], fp16 HMMA.
// CTA = 128(i) x 256(c); j in 64-chunks (4 ksteps), double-buffered cp.async.
// 8 warps = 4(m) x 2(n). grid (32, 4), 256 thr.
// ---------------------------------------------------------------------------
constexpr int PBF16  = 128 * 72;    // 9216 halves
constexpr int VBF16  = 256 * 72;    // 18432 halves
constexpr int ABUF16 = PBF16 + VBF16;

__global__ __launch_bounds__(256)
void av_gemm(float* __restrict__ out)
{
    extern __shared__ char smraw[];
    __half* sh = (__half*)smraw;
    const uint32_t sb = smem_u32(smraw);

    const int t = threadIdx.x;
    const int w = t >> 5, lane = t & 31, g = lane >> 2, tq = lane & 3;
    const int i0 = blockIdx.x * 128;
    const int b  = blockIdx.y;

    const __half* Pb = g_sh + ((size_t)(b * HWSZ + i0)) * HWSZ;
    const __half* Vb = g_vh + (size_t)b * CHN * HWSZ;

    const int wm = w >> 1, wn = w & 1;

    float acc[2][16][4];
    #pragma unroll
    for (int mt = 0; mt < 2; mt++)
        #pragma unroll
        for (int nt = 0; nt < 16; nt++)
            #pragma unroll
            for (int e = 0; e < 4; e++) acc[mt][nt][e] = 0.f;

    auto load_chunk = [&](int it, int buf) {
        uint32_t pb = sb + (uint32_t)(buf * ABUF16) * 2;
        uint32_t vp = pb + (uint32_t)PBF16 * 2;
        #pragma unroll
        for (int p = 0; p < 4; p++) {                // P: 128 x 64 f16 = 1024 cps
            int idx = t + p * 256;
            int row = idx >> 3, c8 = idx & 7;
            cpa16(pb + (uint32_t)(row * 72 + c8 * 8) * 2,
                  Pb + (size_t)row * HWSZ + it * 64 + c8 * 8);
        }
        #pragma unroll
        for (int p = 0; p < 8; p++) {                // V: 256 x 64 f16 = 2048 cps
            int idx = t + p * 256;
            int row = idx >> 3, c8 = idx & 7;
            cpa16(vp + (uint32_t)(row * 72 + c8 * 8) * 2,
                  Vb + (size_t)row * HWSZ + it * 64 + c8 * 8);
        }
        asm volatile("cp.async.commit_group;" ::: "memory");
    };

    load_chunk(0, 0);
    for (int it = 0; it < 64; it++) {
        const int buf = it & 1;
        if (it + 1 < 64) {
            load_chunk(it + 1, buf ^ 1);
            asm volatile("cp.async.wait_group 1;" ::: "memory");
        } else {
            asm volatile("cp.async.wait_group 0;" ::: "memory");
        }
        __syncthreads();

        const __half* Ps = sh + buf * ABUF16;        // [128][72]
        const __half* Vs = Ps + PBF16;               // [256][72]

        #pragma unroll
        for (int kst = 0; kst < 4; kst++) {
            int k0 = kst * 16;
            uint32_t af[2][4];
            #pragma unroll
            for (int mt = 0; mt < 2; mt++) {
                const __half* pp = Ps + (wm * 32 + mt * 16 + g) * 72 + k0;
                af[mt][0] = ldsm_u32(pp + 2 * tq);
                af[mt][1] = ldsm_u32(pp + 8 * 72 + 2 * tq);
                af[mt][2] = ldsm_u32(pp + 2 * tq + 8);
                af[mt][3] = ldsm_u32(pp + 8 * 72 + 2 * tq + 8);
            }
            #pragma unroll
            for (int nt = 0; nt < 16; nt++) {
                const __half* vv = Vs + (wn * 128 + nt * 8 + g) * 72 + k0;
                uint32_t b0 = ldsm_u32(vv + 2 * tq);
                uint32_t b1 = ldsm_u32(vv + 2 * tq + 8);
                mma16(acc[0][nt], af[0], b0, b1);
                mma16(acc[1][nt], af[1], b0, b1);
            }
        }
        __syncthreads();
    }

    // epilogue: fp32 stage [128][132], two channel halves, coalesced stores
    float* stg = (float*)smraw;
    for (int h = 0; h < 2; h++) {
        __syncthreads();
        if (wn == h) {
            #pragma unroll
            for (int mt = 0; mt < 2; mt++) {
                int il = wm * 32 + mt * 16;
                #pragma unroll
                for (int nt = 0; nt < 16; nt++) {
                    int cl = nt * 8 + 2 * tq;
                    stg[cl * 132 + il + g]           = acc[mt][nt][0];
                    stg[(cl + 1) * 132 + il + g]     = acc[mt][nt][1];
                    stg[cl * 132 + il + g + 8]       = acc[mt][nt][2];
                    stg[(cl + 1) * 132 + il + g + 8] = acc[mt][nt][3];
                }
            }
        }
        __syncthreads();
        float* dst = out + ((size_t)(b * CHN + h * 128)) * HWSZ + i0;
        #pragma unroll
        for (int p = 0; p < 16; p++) {
            int idx = t + p * 256;
            int c = idx >> 5, q4 = idx & 31;
            *(float4*)(dst + (size_t)c * HWSZ + 4 * q4) =
                *(const float4*)(stg + c * 132 + 4 * q4);
        }
    }
}

// ---------------------------------------------------------------------------

static constexpr int CONV_SMEM = 2 * CBUF16 * 2;                 // 94464 B
static constexpr int QK_SMEM   = 2 * 128 * 72 * 2;               // 36864 B
static constexpr int AV_SMEM   = 2 * ABUF16 * 2;                 // 110592 B

extern "C" void kernel_launch(void* const* d_in, const int* in_sizes, int n_in,
                              void* d_out, int out_size)
{
    const float* x   = (const float*)d_in[0];
    const float* q_w = (const float*)d_in[1];
    const float* q_b = (const float*)d_in[2];
    const float* k_w = (const float*)d_in[3];
    const float* k_b = (const float*)d_in[4];
    const float* v_w = (const float*)d_in[5];
    const float* v_b = (const float*)d_in[6];
    float* out = (float*)d_out;

    cudaFuncSetAttribute(conv3x3_tc, cudaFuncAttributeMaxDynamicSharedMemorySize, CONV_SMEM);
    cudaFuncSetAttribute(qk_gemm,    cudaFuncAttributeMaxDynamicSharedMemorySize, QK_SMEM);
    cudaFuncSetAttribute(av_gemm,    cudaFuncAttributeMaxDynamicSharedMemorySize, AV_SMEM);

    cvt_x<<<1024, 256>>>(x);
    cvt_w<<<384, 256>>>(q_w, k_w, v_w);
    conv3x3_tc<<<dim3(16, 24), 256, CONV_SMEM>>>(q_b, k_b, v_b);
    qk_gemm<<<dim3(HWSZ / 128, HWSZ / 128, BATCH), 256, QK_SMEM>>>();
    softmax_rows<<<BATCH * HWSZ, 256>>>();
    av_gemm<<<dim3(HWSZ / 128, BATCH), 256, AV_SMEM>>>(out);
}

// round 10
// speedup vs baseline: 18.7285x; 1.0373x over previous
#include <cuda_runtime.h>
#include <cuda_fp16.h>
#include <cstdint>

#define BATCH 4
#define CHN   256
#define CQKD  64
#define HH    64
#define WW    64
#define HWSZ  4096

// fp16 tensors (fp32 accumulate everywhere)
__device__ __align__(16) __half g_xh[BATCH * HWSZ * CHN];          // [b][hw][ci]
__device__ __align__(16) __half g_wh[384 * 9 * CHN];               // [o][tap][ci], q|k|v
__device__ __align__(16) __half g_qh[BATCH * HWSZ * CQKD];         // [b][hw][d], pre-scaled
__device__ __align__(16) __half g_kh[BATCH * HWSZ * CQKD];         // [b][hw][d]
__device__ __align__(16) __half g_vh[BATCH * CHN * HWSZ];          // [b][c][hw]
__device__ __align__(16) __half g_sh[(size_t)BATCH * HWSZ * HWSZ]; // logits -> probs

// ---------------- helpers ----------------
__device__ __forceinline__ void mma16(float* c, const uint32_t* a,
                                      uint32_t b0, uint32_t b1) {
    asm volatile("mma.sync.aligned.m16n8k16.row.col.f32.f16.f16.f32 "
        "{%0,%1,%2,%3}, {%4,%5,%6,%7}, {%8,%9}, {%0,%1,%2,%3};"
        : "+f"(c[0]), "+f"(c[1]), "+f"(c[2]), "+f"(c[3])
        : "r"(a[0]), "r"(a[1]), "r"(a[2]), "r"(a[3]), "r"(b0), "r"(b1));
}
__device__ __forceinline__ void ldsm4(uint32_t& r0, uint32_t& r1,
                                      uint32_t& r2, uint32_t& r3, uint32_t a) {
    asm volatile("ldmatrix.sync.aligned.m8n8.x4.shared.b16 {%0,%1,%2,%3}, [%4];"
        : "=r"(r0), "=r"(r1), "=r"(r2), "=r"(r3) : "r"(a));
}
__device__ __forceinline__ void cpa16(uint32_t saddr, const void* g) {
    asm volatile("cp.async.cg.shared.global [%0], [%1], 16;"
                 :: "r"(saddr), "l"(g) : "memory");
}
__device__ __forceinline__ uint32_t smem_u32(const void* p) {
    return (uint32_t)__cvta_generic_to_shared((void*)p);
}

// ---------------------------------------------------------------------------
// K0a: transpose+convert x: [b][ci][hw] fp32 -> [b][hw][ci] fp16.
// ---------------------------------------------------------------------------
__global__ __launch_bounds__(256)
void cvt_x(const float* __restrict__ x)
{
    __shared__ __half ts[64][72];
    const int t = threadIdx.x;
    const int blk = blockIdx.x;
    const int b = blk >> 8, r = blk & 255;
    const int ci0 = (r >> 6) * 64, hw0 = (r & 63) * 64;

    #pragma unroll
    for (int p = 0; p < 4; p++) {
        int idx = t + p * 256;
        int ci = idx >> 4, hq = idx & 15;
        float4 v = *(const float4*)(x + ((size_t)(b * CHN + ci0 + ci)) * HWSZ + hw0 + 4 * hq);
        ts[ci][4 * hq + 0] = __float2half_rn(v.x);
        ts[ci][4 * hq + 1] = __float2half_rn(v.y);
        ts[ci][4 * hq + 2] = __float2half_rn(v.z);
        ts[ci][4 * hq + 3] = __float2half_rn(v.w);
    }
    __syncthreads();
    #pragma unroll
    for (int p = 0; p < 2; p++) {
        int idx = t + p * 256;
        int hw = idx >> 3, c8 = idx & 7;
        union { __half h[8]; uint4 u; } pk;
        #pragma unroll
        for (int e = 0; e < 8; e++) pk.h[e] = ts[c8 * 8 + e][hw];
        *(uint4*)(g_xh + ((size_t)(b * HWSZ + hw0 + hw)) * CHN + ci0 + c8 * 8) = pk.u;
    }
}

// ---------------------------------------------------------------------------
// K0b: weights [o][ci][9] fp32 -> [o][tap][ci] fp16.
// ---------------------------------------------------------------------------
__global__ __launch_bounds__(256)
void cvt_w(const float* __restrict__ qw, const float* __restrict__ kw,
           const float* __restrict__ vw)
{
    const int o = blockIdx.x, t = threadIdx.x;
    const float* w; int ol;
    if (o < 64)       { w = qw; ol = o; }
    else if (o < 128) { w = kw; ol = o - 64; }
    else              { w = vw; ol = o - 128; }
    #pragma unroll
    for (int tap = 0; tap < 9; tap++)
        g_wh[((size_t)o * 9 + tap) * CHN + t] =
            __float2half_rn(w[((size_t)ol * CHN + t) * 9 + tap]);
}

// ---------------------------------------------------------------------------
// K1: 3x3 conv as implicit GEMM, fp16 HMMA + ldmatrix. CTA: 64 oc x 256 spat.
// ---------------------------------------------------------------------------
constexpr int CIP    = 24;                  // padded ci stride (fp16)
constexpr int XSF16  = 6 * 68 * CIP;        // 9792 halves
constexpr int WSF16  = 64 * 9 * CIP;        // 13824 halves
constexpr int CBUF16 = XSF16 + WSF16;       // 23616 halves

__global__ __launch_bounds__(256)
void conv3x3_tc(const float* __restrict__ qb, const float* __restrict__ kb,
                const float* __restrict__ vb)
{
    extern __shared__ char smraw[];
    __half* sh = (__half*)smraw;
    const uint32_t sb = smem_u32(smraw);

    const int t = threadIdx.x;
    const int w = t >> 5, lane = t & 31, g = lane >> 2, tq = lane & 3;
    const int r8 = lane & 7, q4d = lane >> 3;      // ldmatrix quadrant decoding
    const int y0  = blockIdx.x * 4;
    const int hw0 = y0 * WW;
    const int zz  = blockIdx.y;
    const int b   = zz / 6, og = zz % 6;

    const float* bias; int wo0, o0l, kind;
    if (og == 0)      { bias = qb; wo0 = 0;                  o0l = 0;             kind = 0; }
    else if (og == 1) { bias = kb; wo0 = 64;                 o0l = 0;             kind = 1; }
    else              { bias = vb; wo0 = 128 + (og - 2) * 64; o0l = (og - 2) * 64; kind = 2; }

    const int wm = w >> 2, wn = w & 3;

    // zero halo cols (>=64) and out-of-image rows, both buffers
    {
        const uint4 z = make_uint4(0, 0, 0, 0);
        for (int idx = t; idx < 2 * 6 * 68 * 2; idx += 256) {
            int buf = idx / 816, rcq = idx % 816;
            int row = rcq / 136, cc = rcq % 136;
            int col = cc >> 1, ci8 = cc & 1;
            int gy = y0 - 1 + row;
            if (col >= 64 || (unsigned)gy >= (unsigned)HH)
                *(uint4*)(sh + buf * CBUF16 + (row * 68 + col) * CIP + ci8 * 8) = z;
        }
    }
    __syncthreads();

    auto prefetch = [&](int c0, int buf) {
        uint32_t xd = sb + (uint32_t)(buf * CBUF16) * 2;
        uint32_t wd = xd + (uint32_t)XSF16 * 2;
        #pragma unroll
        for (int p = 0; p < 3; p++) {                   // x: 768 cps
            int idx = t + p * 256;
            int ci8 = idx & 1, col = (idx >> 1) & 63, row = idx >> 7;
            int gy = y0 - 1 + row;
            if ((unsigned)gy < (unsigned)HH) {
                const __half* src = g_xh + ((size_t)(b * HWSZ + gy * WW + col)) * CHN + c0 + ci8 * 8;
                uint32_t dst = xd + (uint32_t)((row * 68 + col) * CIP + ci8 * 8) * 2;
                cpa16(dst, src);
            }
        }
        #pragma unroll
        for (int p = 0; p < 5; p++) {                   // w: 1152 cps
            int idx = t + p * 256;
            if (idx < 1152) {
                int ci8 = idx & 1, r = idx >> 1;
                int o = r / 9, kk = r % 9;
                const __half* src = g_wh + ((size_t)(wo0 + o) * 9 + kk) * CHN + c0 + ci8 * 8;
                uint32_t dst = wd + (uint32_t)((o * 9 + kk) * CIP + ci8 * 8) * 2;
                cpa16(dst, src);
            }
        }
        asm volatile("cp.async.commit_group;" ::: "memory");
    };

    float acc[2][8][4];
    #pragma unroll
    for (int mt = 0; mt < 2; mt++)
        #pragma unroll
        for (int nt = 0; nt < 8; nt++)
            #pragma unroll
            for (int e = 0; e < 4; e++) acc[mt][nt][e] = 0.f;

    prefetch(0, 0);
    for (int c = 0; c < 16; c++) {
        const int buf = c & 1;
        if (c + 1 < 16) {
            prefetch((c + 1) * 16, buf ^ 1);
            asm volatile("cp.async.wait_group 1;" ::: "memory");
        } else {
            asm volatile("cp.async.wait_group 0;" ::: "memory");
        }
        __syncthreads();

        const uint32_t xd = sb + (uint32_t)(buf * CBUF16) * 2;
        const uint32_t wd = xd + (uint32_t)XSF16 * 2;

        #pragma unroll
        for (int kk = 0; kk < 9; kk++) {
            const int ky = kk / 3, kx = kk - 3 * ky;
            uint32_t af[2][4];
            #pragma unroll
            for (int mt = 0; mt < 2; mt++) {
                int o = wm * 32 + mt * 16 + r8 + (q4d & 1) * 8;
                uint32_t addr = wd + (uint32_t)((o * 9 + kk) * CIP + (q4d >> 1) * 8) * 2;
                ldsm4(af[mt][0], af[mt][1], af[mt][2], af[mt][3], addr);
            }
            #pragma unroll
            for (int np = 0; np < 4; np++) {
                int cidx = np * 16 + ((lane >> 4) * 8) + r8;     // 0..63 spatial col
                int icol = cidx + kx - 1;
                int col  = ((unsigned)icol < 64u) ? icol : 64;   // 64 = zero slot
                uint32_t addr = xd + (uint32_t)(((wn + ky) * 68 + col) * CIP
                                                + ((lane >> 3) & 1) * 8) * 2;
                uint32_t b0, b1, b2, b3;
                ldsm4(b0, b1, b2, b3, addr);
                mma16(acc[0][2 * np],     af[0], b0, b1);
                mma16(acc[1][2 * np],     af[1], b0, b1);
                mma16(acc[0][2 * np + 1], af[0], b2, b3);
                mma16(acc[1][2 * np + 1], af[1], b2, b3);
            }
        }
        __syncthreads();
    }

    // epilogue: bias (+scale), convert fp16, stage, coalesced store
    __half* stg = sh;
    if (kind < 2) {
        __half* outg = (kind == 0) ? g_qh : g_kh;
        const float sc = (kind == 0) ? 0.125f : 1.f;
        #pragma unroll
        for (int mt = 0; mt < 2; mt++) {
            int ob = wm * 32 + mt * 16 + g;
            float b0v = bias[ob], b1v = bias[ob + 8];
            #pragma unroll
            for (int nt = 0; nt < 8; nt++) {
                int n0 = wn * 64 + nt * 8 + 2 * tq;
                stg[n0 * 72 + ob]           = __float2half_rn((acc[mt][nt][0] + b0v) * sc);
                stg[(n0 + 1) * 72 + ob]     = __float2half_rn((acc[mt][nt][1] + b0v) * sc);
                stg[n0 * 72 + ob + 8]       = __float2half_rn((acc[mt][nt][2] + b1v) * sc);
                stg[(n0 + 1) * 72 + ob + 8] = __float2half_rn((acc[mt][nt][3] + b1v) * sc);
            }
        }
        __syncthreads();
        #pragma unroll
        for (int p = 0; p < 8; p++) {
            int idx = t + p * 256;
            int n = idx >> 3, q8 = idx & 7;
            *(uint4*)(outg + ((size_t)(b * HWSZ + hw0 + n)) * CQKD + q8 * 8) =
                *(const uint4*)(stg + n * 72 + q8 * 8);
        }
    } else {
        #pragma unroll
        for (int mt = 0; mt < 2; mt++) {
            int ob = wm * 32 + mt * 16 + g;
            float b0v = bias[o0l + ob], b1v = bias[o0l + ob + 8];
            #pragma unroll
            for (int nt = 0; nt < 8; nt++) {
                int n0 = wn * 64 + nt * 8 + 2 * tq;
                *(__half2*)(stg + ob * 264 + n0) =
                    __floats2half2_rn(acc[mt][nt][0] + b0v, acc[mt][nt][1] + b0v);
                *(__half2*)(stg + (ob + 8) * 264 + n0) =
                    __floats2half2_rn(acc[mt][nt][2] + b1v, acc[mt][nt][3] + b1v);
            }
        }
        __syncthreads();
        #pragma unroll
        for (int p = 0; p < 8; p++) {
            int idx = t + p * 256;
            int o = idx >> 5, q8 = idx & 31;
            *(uint4*)(g_vh + ((size_t)(b * CHN + o0l + o)) * HWSZ + hw0 + q8 * 8) =
                *(const uint4*)(stg + o * 264 + q8 * 8);
        }
    }
}

// ---------------------------------------------------------------------------
// K2: S = Q^T K, fp16 HMMA + ldmatrix. CTA = 128(i) x 128(j), k = 64.
// ---------------------------------------------------------------------------
__global__ __launch_bounds__(256)
void qk_gemm()
{
    extern __shared__ char smraw[];
    __half* sh = (__half*)smraw;
    const uint32_t sb = smem_u32(smraw);
    __half* qs = sh;
    __half* ks = sh + 128 * 72;

    const int t = threadIdx.x;
    const int w = t >> 5, lane = t & 31, g = lane >> 2, tq = lane & 3;
    const int r8 = lane & 7, q4d = lane >> 3;
    const int j0 = blockIdx.x * 128;
    const int i0 = blockIdx.y * 128;
    const int b  = blockIdx.z;

    #pragma unroll
    for (int p = 0; p < 8; p++) {
        int idx = t + p * 256;
        int arr = idx >> 10, r2 = idx & 1023;
        int row = r2 >> 3, q8 = r2 & 7;
        const __half* src = (arr ? g_kh + ((size_t)(b * HWSZ + j0 + row)) * CQKD
                                 : g_qh + ((size_t)(b * HWSZ + i0 + row)) * CQKD) + q8 * 8;
        __half* dst = (arr ? ks : qs) + row * 72 + q8 * 8;
        *(uint4*)dst = *(const uint4*)src;
    }
    __syncthreads();

    const int wm = w >> 1, wn = w & 1;
    const uint32_t sqs = sb;
    const uint32_t sks = sb + 128 * 72 * 2;

    float acc[2][8][4];
    #pragma unroll
    for (int mt = 0; mt < 2; mt++)
        #pragma unroll
        for (int nt = 0; nt < 8; nt++)
            #pragma unroll
            for (int e = 0; e < 4; e++) acc[mt][nt][e] = 0.f;

    #pragma unroll
    for (int kst = 0; kst < 4; kst++) {
        int k0 = kst * 16;
        uint32_t af[2][4];
        #pragma unroll
        for (int mt = 0; mt < 2; mt++) {
            int row = wm * 32 + mt * 16 + r8 + (q4d & 1) * 8;
            uint32_t addr = sqs + (uint32_t)(row * 72 + k0 + (q4d >> 1) * 8) * 2;
            ldsm4(af[mt][0], af[mt][1], af[mt][2], af[mt][3], addr);
        }
        #pragma unroll
        for (int np = 0; np < 4; np++) {
            int row = wn * 64 + np * 16 + ((lane >> 4) * 8) + r8;
            uint32_t addr = sks + (uint32_t)(row * 72 + k0 + ((lane >> 3) & 1) * 8) * 2;
            uint32_t b0, b1, b2, b3;
            ldsm4(b0, b1, b2, b3, addr);
            mma16(acc[0][2 * np],     af[0], b0, b1);
            mma16(acc[1][2 * np],     af[1], b0, b1);
            mma16(acc[0][2 * np + 1], af[0], b2, b3);
            mma16(acc[1][2 * np + 1], af[1], b2, b3);
        }
    }
    __syncthreads();

    __half* stg = sh;    // [128][136]
    #pragma unroll
    for (int mt = 0; mt < 2; mt++) {
        int r0 = wm * 32 + mt * 16;
        #pragma unroll
        for (int nt = 0; nt < 8; nt++) {
            int cc = wn * 64 + nt * 8 + 2 * tq;
            *(__half2*)(stg + (r0 + g) * 136 + cc) =
                __floats2half2_rn(acc[mt][nt][0], acc[mt][nt][1]);
            *(__half2*)(stg + (r0 + g + 8) * 136 + cc) =
                __floats2half2_rn(acc[mt][nt][2], acc[mt][nt][3]);
        }
    }
    __syncthreads();
    #pragma unroll
    for (int p = 0; p < 8; p++) {
        int idx = t + p * 256;
        int row = idx >> 4, q8 = idx & 15;
        *(uint4*)(g_sh + ((size_t)(b * HWSZ + i0 + row)) * HWSZ + j0 + q8 * 8) =
            *(const uint4*)(stg + row * 136 + q8 * 8);
    }
}

// ---------------------------------------------------------------------------
// K3: in-place fp16 row softmax over g_sh (fp32 math).
// ---------------------------------------------------------------------------
__global__ __launch_bounds__(256)
void softmax_rows()
{
    __shared__ float red[8];
    const int t = threadIdx.x;
    const int w = t >> 5, lane = t & 31;
    __half* row = g_sh + (size_t)blockIdx.x * HWSZ;

    uint4 v[2];
    float x[16];
    #pragma unroll
    for (int p = 0; p < 2; p++) v[p] = ((const uint4*)row)[t + 256 * p];
    #pragma unroll
    for (int p = 0; p < 2; p++) {
        const uint32_t* u = (const uint32_t*)&v[p];
        #pragma unroll
        for (int q = 0; q < 4; q++) {
            float2 f = __half22float2(*(const __half2*)&u[q]);
            x[p * 8 + q * 2]     = f.x;
            x[p * 8 + q * 2 + 1] = f.y;
        }
    }

    float m = x[0];
    #pragma unroll
    for (int i = 1; i < 16; i++) m = fmaxf(m, x[i]);
    #pragma unroll
    for (int off = 16; off; off >>= 1) m = fmaxf(m, __shfl_xor_sync(~0u, m, off));
    if (lane == 0) red[w] = m;
    __syncthreads();
    m = red[0];
    #pragma unroll
    for (int i = 1; i < 8; i++) m = fmaxf(m, red[i]);
    __syncthreads();

    float s = 0.f;
    #pragma unroll
    for (int i = 0; i < 16; i++) { x[i] = __expf(x[i] - m); s += x[i]; }
    #pragma unroll
    for (int off = 16; off; off >>= 1) s += __shfl_xor_sync(~0u, s, off);
    if (lane == 0) red[w] = s;
    __syncthreads();
    s = red[0];
    #pragma unroll
    for (int i = 1; i < 8; i++) s += red[i];
    const float inv = 1.f / s;

    #pragma unroll
    for (int p = 0; p < 2; p++) {
        uint32_t* u = (uint32_t*)&v[p];
        #pragma unroll
        for (int q = 0; q < 4; q++) {
            __half2 hh = __floats2half2_rn(x[p * 8 + q * 2] * inv,
                                           x[p * 8 + q * 2 + 1] * inv);
            u[q] = *(const uint32_t*)&hh;
        }
        ((uint4*)row)[t + 256 * p] = v[p];
    }
}

// ---------------------------------------------------------------------------
// K4: out = P V^T, fp16 HMMA + ldmatrix. CTA = 128(i) x 256(c); 64-j chunks,
// double-buffered cp.async. 8 warps = 4(m) x 2(n). grid (32, 4), 256 thr.
// ---------------------------------------------------------------------------
constexpr int PBF16  = 128 * 72;
constexpr int VBF16  = 256 * 72;
constexpr int ABUF16 = PBF16 + VBF16;

__global__ __launch_bounds__(256)
void av_gemm(float* __restrict__ out)
{
    extern __shared__ char smraw[];
    __half* sh = (__half*)smraw;
    const uint32_t sb = smem_u32(smraw);

    const int t = threadIdx.x;
    const int w = t >> 5, lane = t & 31, g = lane >> 2, tq = lane & 3;
    const int r8 = lane & 7, q4d = lane >> 3;
    const int i0 = blockIdx.x * 128;
    const int b  = blockIdx.y;

    const __half* Pb = g_sh + ((size_t)(b * HWSZ + i0)) * HWSZ;
    const __half* Vb = g_vh + (size_t)b * CHN * HWSZ;

    const int wm = w >> 1, wn = w & 1;

    float acc[2][16][4];
    #pragma unroll
    for (int mt = 0; mt < 2; mt++)
        #pragma unroll
        for (int nt = 0; nt < 16; nt++)
            #pragma unroll
            for (int e = 0; e < 4; e++) acc[mt][nt][e] = 0.f;

    auto load_chunk = [&](int it, int buf) {
        uint32_t pb = sb + (uint32_t)(buf * ABUF16) * 2;
        uint32_t vp = pb + (uint32_t)PBF16 * 2;
        #pragma unroll
        for (int p = 0; p < 4; p++) {
            int idx = t + p * 256;
            int row = idx >> 3, c8 = idx & 7;
            cpa16(pb + (uint32_t)(row * 72 + c8 * 8) * 2,
                  Pb + (size_t)row * HWSZ + it * 64 + c8 * 8);
        }
        #pragma unroll
        for (int p = 0; p < 8; p++) {
            int idx = t + p * 256;
            int row = idx >> 3, c8 = idx & 7;
            cpa16(vp + (uint32_t)(row * 72 + c8 * 8) * 2,
                  Vb + (size_t)row * HWSZ + it * 64 + c8 * 8);
        }
        asm volatile("cp.async.commit_group;" ::: "memory");
    };

    load_chunk(0, 0);
    for (int it = 0; it < 64; it++) {
        const int buf = it & 1;
        if (it + 1 < 64) {
            load_chunk(it + 1, buf ^ 1);
            asm volatile("cp.async.wait_group 1;" ::: "memory");
        } else {
            asm volatile("cp.async.wait_group 0;" ::: "memory");
        }
        __syncthreads();

        const uint32_t pd = sb + (uint32_t)(buf * ABUF16) * 2;
        const uint32_t vd = pd + (uint32_t)PBF16 * 2;

        #pragma unroll
        for (int kst = 0; kst < 4; kst++) {
            int k0 = kst * 16;
            uint32_t af[2][4];
            #pragma unroll
            for (int mt = 0; mt < 2; mt++) {
                int row = wm * 32 + mt * 16 + r8 + (q4d & 1) * 8;
                uint32_t addr = pd + (uint32_t)(row * 72 + k0 + (q4d >> 1) * 8) * 2;
                ldsm4(af[mt][0], af[mt][1], af[mt][2], af[mt][3], addr);
            }
            #pragma unroll
            for (int np = 0; np < 8; np++) {
                int row = wn * 128 + np * 16 + ((lane >> 4) * 8) + r8;
                uint32_t addr = vd + (uint32_t)(row * 72 + k0 + ((lane >> 3) & 1) * 8) * 2;
                uint32_t b0, b1, b2, b3;
                ldsm4(b0, b1, b2, b3, addr);
                mma16(acc[0][2 * np],     af[0], b0, b1);
                mma16(acc[1][2 * np],     af[1], b0, b1);
                mma16(acc[0][2 * np + 1], af[0], b2, b3);
                mma16(acc[1][2 * np + 1], af[1], b2, b3);
            }
        }
        __syncthreads();
    }

    // epilogue: fp32 stage [128][132], two channel halves, coalesced stores
    float* stg = (float*)smraw;
    for (int h = 0; h < 2; h++) {
        __syncthreads();
        if (wn == h) {
            #pragma unroll
            for (int mt = 0; mt < 2; mt++) {
                int il = wm * 32 + mt * 16;
                #pragma unroll
                for (int nt = 0; nt < 16; nt++) {
                    int cl = nt * 8 + 2 * tq;
                    stg[cl * 132 + il + g]           = acc[mt][nt][0];
                    stg[(cl + 1) * 132 + il + g]     = acc[mt][nt][1];
                    stg[cl * 132 + il + g + 8]       = acc[mt][nt][2];
                    stg[(cl + 1) * 132 + il + g + 8] = acc[mt][nt][3];
                }
            }
        }
        __syncthreads();
        float* dst = out + ((size_t)(b * CHN + h * 128)) * HWSZ + i0;
        #pragma unroll
        for (int p = 0; p < 16; p++) {
            int idx = t + p * 256;
            int c = idx >> 5, q4 = idx & 31;
            *(float4*)(dst + (size_t)c * HWSZ + 4 * q4) =
                *(const float4*)(stg + c * 132 + 4 * q4);
        }
    }
}

// ---------------------------------------------------------------------------

static constexpr int CONV_SMEM = 2 * CBUF16 * 2;                 // 94464 B
static constexpr int QK_SMEM   = 2 * 128 * 72 * 2;               // 36864 B
static constexpr int AV_SMEM   = 2 * ABUF16 * 2;                 // 110592 B

extern "C" void kernel_launch(void* const* d_in, const int* in_sizes, int n_in,
                              void* d_out, int out_size)
{
    const float* x   = (const float*)d_in[0];
    const float* q_w = (const float*)d_in[1];
    const float* q_b = (const float*)d_in[2];
    const float* k_w = (const float*)d_in[3];
    const float* k_b = (const float*)d_in[4];
    const float* v_w = (const float*)d_in[5];
    const float* v_b = (const float*)d_in[6];
    float* out = (float*)d_out;

    cudaFuncSetAttribute(conv3x3_tc, cudaFuncAttributeMaxDynamicSharedMemorySize, CONV_SMEM);
    cudaFuncSetAttribute(qk_gemm,    cudaFuncAttributeMaxDynamicSharedMemorySize, QK_SMEM);
    cudaFuncSetAttribute(av_gemm,    cudaFuncAttributeMaxDynamicSharedMemorySize, AV_SMEM);

    cvt_x<<<1024, 256>>>(x);
    cvt_w<<<384, 256>>>(q_w, k_w, v_w);
    conv3x3_tc<<<dim3(16, 24), 256, CONV_SMEM>>>(q_b, k_b, v_b);
    qk_gemm<<<dim3(HWSZ / 128, HWSZ / 128, BATCH), 256, QK_SMEM>>>();
    softmax_rows<<<BATCH * HWSZ, 256>>>();
    av_gemm<<<dim3(HWSZ / 128, BATCH), 256, AV_SMEM>>>(out);
}

// round 11
// speedup vs baseline: 23.2593x; 1.2419x over previous
#include <cuda_runtime.h>
#include <cuda_fp16.h>
#include <cstdint>

#define BATCH 4
#define CHN   256
#define CQKD  64
#define HH    64
#define WW    64
#define HWSZ  4096

// fp16 tensors (fp32 accumulate everywhere)
__device__ __align__(16) __half g_xh[BATCH * HWSZ * CHN];          // [b][hw][ci]
__device__ __align__(16) __half g_wh[384 * 9 * CHN];               // [o][tap][ci], q|k|v
__device__ __align__(16) __half g_qh[BATCH * HWSZ * CQKD];         // [b][hw][d], pre-scaled
__device__ __align__(16) __half g_kh[BATCH * HWSZ * CQKD];         // [b][hw][d]
__device__ __align__(16) __half g_vh[BATCH * CHN * HWSZ];          // [b][c][hw]

// ---------------- helpers ----------------
__device__ __forceinline__ void mma16(float* c, const uint32_t* a,
                                      uint32_t b0, uint32_t b1) {
    asm volatile("mma.sync.aligned.m16n8k16.row.col.f32.f16.f16.f32 "
        "{%0,%1,%2,%3}, {%4,%5,%6,%7}, {%8,%9}, {%0,%1,%2,%3};"
        : "+f"(c[0]), "+f"(c[1]), "+f"(c[2]), "+f"(c[3])
        : "r"(a[0]), "r"(a[1]), "r"(a[2]), "r"(a[3]), "r"(b0), "r"(b1));
}
__device__ __forceinline__ void ldsm4(uint32_t& r0, uint32_t& r1,
                                      uint32_t& r2, uint32_t& r3, uint32_t a) {
    asm volatile("ldmatrix.sync.aligned.m8n8.x4.shared.b16 {%0,%1,%2,%3}, [%4];"
        : "=r"(r0), "=r"(r1), "=r"(r2), "=r"(r3) : "r"(a));
}
__device__ __forceinline__ void cpa16(uint32_t saddr, const void* g) {
    asm volatile("cp.async.cg.shared.global [%0], [%1], 16;"
                 :: "r"(saddr), "l"(g) : "memory");
}
__device__ __forceinline__ uint32_t smem_u32(const void* p) {
    return (uint32_t)__cvta_generic_to_shared((void*)p);
}
__device__ __forceinline__ uint32_t h2bits(__half2 h) {
    return *(const uint32_t*)&h;
}

// ---------------------------------------------------------------------------
// K0a: transpose+convert x: [b][ci][hw] fp32 -> [b][hw][ci] fp16.
// ---------------------------------------------------------------------------
__global__ __launch_bounds__(256)
void cvt_x(const float* __restrict__ x)
{
    __shared__ __half ts[64][72];
    const int t = threadIdx.x;
    const int blk = blockIdx.x;
    const int b = blk >> 8, r = blk & 255;
    const int ci0 = (r >> 6) * 64, hw0 = (r & 63) * 64;

    #pragma unroll
    for (int p = 0; p < 4; p++) {
        int idx = t + p * 256;
        int ci = idx >> 4, hq = idx & 15;
        float4 v = *(const float4*)(x + ((size_t)(b * CHN + ci0 + ci)) * HWSZ + hw0 + 4 * hq);
        ts[ci][4 * hq + 0] = __float2half_rn(v.x);
        ts[ci][4 * hq + 1] = __float2half_rn(v.y);
        ts[ci][4 * hq + 2] = __float2half_rn(v.z);
        ts[ci][4 * hq + 3] = __float2half_rn(v.w);
    }
    __syncthreads();
    #pragma unroll
    for (int p = 0; p < 2; p++) {
        int idx = t + p * 256;
        int hw = idx >> 3, c8 = idx & 7;
        union { __half h[8]; uint4 u; } pk;
        #pragma unroll
        for (int e = 0; e < 8; e++) pk.h[e] = ts[c8 * 8 + e][hw];
        *(uint4*)(g_xh + ((size_t)(b * HWSZ + hw0 + hw)) * CHN + ci0 + c8 * 8) = pk.u;
    }
}

// ---------------------------------------------------------------------------
// K0b: weights [o][ci][9] fp32 -> [o][tap][ci] fp16.
// ---------------------------------------------------------------------------
__global__ __launch_bounds__(256)
void cvt_w(const float* __restrict__ qw, const float* __restrict__ kw,
           const float* __restrict__ vw)
{
    const int o = blockIdx.x, t = threadIdx.x;
    const float* w; int ol;
    if (o < 64)       { w = qw; ol = o; }
    else if (o < 128) { w = kw; ol = o - 64; }
    else              { w = vw; ol = o - 128; }
    #pragma unroll
    for (int tap = 0; tap < 9; tap++)
        g_wh[((size_t)o * 9 + tap) * CHN + t] =
            __float2half_rn(w[((size_t)ol * CHN + t) * 9 + tap]);
}

// ---------------------------------------------------------------------------
// K1: 3x3 conv as implicit GEMM, fp16 HMMA + ldmatrix (unchanged from R10).
// ---------------------------------------------------------------------------
constexpr int CIP    = 24;
constexpr int XSF16  = 6 * 68 * CIP;        // 9792 halves
constexpr int WSF16  = 64 * 9 * CIP;        // 13824 halves
constexpr int CBUF16 = XSF16 + WSF16;       // 23616 halves

__global__ __launch_bounds__(256)
void conv3x3_tc(const float* __restrict__ qb, const float* __restrict__ kb,
                const float* __restrict__ vb)
{
    extern __shared__ char smraw[];
    __half* sh = (__half*)smraw;
    const uint32_t sb = smem_u32(smraw);

    const int t = threadIdx.x;
    const int w = t >> 5, lane = t & 31, g = lane >> 2, tq = lane & 3;
    const int r8 = lane & 7, q4d = lane >> 3;
    const int y0  = blockIdx.x * 4;
    const int hw0 = y0 * WW;
    const int zz  = blockIdx.y;
    const int b   = zz / 6, og = zz % 6;

    const float* bias; int wo0, o0l, kind;
    if (og == 0)      { bias = qb; wo0 = 0;                  o0l = 0;             kind = 0; }
    else if (og == 1) { bias = kb; wo0 = 64;                 o0l = 0;             kind = 1; }
    else              { bias = vb; wo0 = 128 + (og - 2) * 64; o0l = (og - 2) * 64; kind = 2; }

    const int wm = w >> 2, wn = w & 3;

    {
        const uint4 z = make_uint4(0, 0, 0, 0);
        for (int idx = t; idx < 2 * 6 * 68 * 2; idx += 256) {
            int buf = idx / 816, rcq = idx % 816;
            int row = rcq / 136, cc = rcq % 136;
            int col = cc >> 1, ci8 = cc & 1;
            int gy = y0 - 1 + row;
            if (col >= 64 || (unsigned)gy >= (unsigned)HH)
                *(uint4*)(sh + buf * CBUF16 + (row * 68 + col) * CIP + ci8 * 8) = z;
        }
    }
    __syncthreads();

    auto prefetch = [&](int c0, int buf) {
        uint32_t xd = sb + (uint32_t)(buf * CBUF16) * 2;
        uint32_t wd = xd + (uint32_t)XSF16 * 2;
        #pragma unroll
        for (int p = 0; p < 3; p++) {
            int idx = t + p * 256;
            int ci8 = idx & 1, col = (idx >> 1) & 63, row = idx >> 7;
            int gy = y0 - 1 + row;
            if ((unsigned)gy < (unsigned)HH) {
                const __half* src = g_xh + ((size_t)(b * HWSZ + gy * WW + col)) * CHN + c0 + ci8 * 8;
                uint32_t dst = xd + (uint32_t)((row * 68 + col) * CIP + ci8 * 8) * 2;
                cpa16(dst, src);
            }
        }
        #pragma unroll
        for (int p = 0; p < 5; p++) {
            int idx = t + p * 256;
            if (idx < 1152) {
                int ci8 = idx & 1, r = idx >> 1;
                int o = r / 9, kk = r % 9;
                const __half* src = g_wh + ((size_t)(wo0 + o) * 9 + kk) * CHN + c0 + ci8 * 8;
                uint32_t dst = wd + (uint32_t)((o * 9 + kk) * CIP + ci8 * 8) * 2;
                cpa16(dst, src);
            }
        }
        asm volatile("cp.async.commit_group;" ::: "memory");
    };

    float acc[2][8][4];
    #pragma unroll
    for (int mt = 0; mt < 2; mt++)
        #pragma unroll
        for (int nt = 0; nt < 8; nt++)
            #pragma unroll
            for (int e = 0; e < 4; e++) acc[mt][nt][e] = 0.f;

    prefetch(0, 0);
    for (int c = 0; c < 16; c++) {
        const int buf = c & 1;
        if (c + 1 < 16) {
            prefetch((c + 1) * 16, buf ^ 1);
            asm volatile("cp.async.wait_group 1;" ::: "memory");
        } else {
            asm volatile("cp.async.wait_group 0;" ::: "memory");
        }
        __syncthreads();

        const uint32_t xd = sb + (uint32_t)(buf * CBUF16) * 2;
        const uint32_t wd = xd + (uint32_t)XSF16 * 2;

        #pragma unroll
        for (int kk = 0; kk < 9; kk++) {
            const int ky = kk / 3, kx = kk - 3 * ky;
            uint32_t af[2][4];
            #pragma unroll
            for (int mt = 0; mt < 2; mt++) {
                int o = wm * 32 + mt * 16 + r8 + (q4d & 1) * 8;
                uint32_t addr = wd + (uint32_t)((o * 9 + kk) * CIP + (q4d >> 1) * 8) * 2;
                ldsm4(af[mt][0], af[mt][1], af[mt][2], af[mt][3], addr);
            }
            #pragma unroll
            for (int np = 0; np < 4; np++) {
                int cidx = np * 16 + ((lane >> 4) * 8) + r8;
                int icol = cidx + kx - 1;
                int col  = ((unsigned)icol < 64u) ? icol : 64;
                uint32_t addr = xd + (uint32_t)(((wn + ky) * 68 + col) * CIP
                                                + ((lane >> 3) & 1) * 8) * 2;
                uint32_t b0, b1, b2, b3;
                ldsm4(b0, b1, b2, b3, addr);
                mma16(acc[0][2 * np],     af[0], b0, b1);
                mma16(acc[1][2 * np],     af[1], b0, b1);
                mma16(acc[0][2 * np + 1], af[0], b2, b3);
                mma16(acc[1][2 * np + 1], af[1], b2, b3);
            }
        }
        __syncthreads();
    }

    __half* stg = sh;
    if (kind < 2) {
        __half* outg = (kind == 0) ? g_qh : g_kh;
        const float sc = (kind == 0) ? 0.125f : 1.f;
        #pragma unroll
        for (int mt = 0; mt < 2; mt++) {
            int ob = wm * 32 + mt * 16 + g;
            float b0v = bias[ob], b1v = bias[ob + 8];
            #pragma unroll
            for (int nt = 0; nt < 8; nt++) {
                int n0 = wn * 64 + nt * 8 + 2 * tq;
                stg[n0 * 72 + ob]           = __float2half_rn((acc[mt][nt][0] + b0v) * sc);
                stg[(n0 + 1) * 72 + ob]     = __float2half_rn((acc[mt][nt][1] + b0v) * sc);
                stg[n0 * 72 + ob + 8]       = __float2half_rn((acc[mt][nt][2] + b1v) * sc);
                stg[(n0 + 1) * 72 + ob + 8] = __float2half_rn((acc[mt][nt][3] + b1v) * sc);
            }
        }
        __syncthreads();
        #pragma unroll
        for (int p = 0; p < 8; p++) {
            int idx = t + p * 256;
            int n = idx >> 3, q8 = idx & 7;
            *(uint4*)(outg + ((size_t)(b * HWSZ + hw0 + n)) * CQKD + q8 * 8) =
                *(const uint4*)(stg + n * 72 + q8 * 8);
        }
    } else {
        #pragma unroll
        for (int mt = 0; mt < 2; mt++) {
            int ob = wm * 32 + mt * 16 + g;
            float b0v = bias[o0l + ob], b1v = bias[o0l + ob + 8];
            #pragma unroll
            for (int nt = 0; nt < 8; nt++) {
                int n0 = wn * 64 + nt * 8 + 2 * tq;
                *(__half2*)(stg + ob * 264 + n0) =
                    __floats2half2_rn(acc[mt][nt][0] + b0v, acc[mt][nt][1] + b0v);
                *(__half2*)(stg + (ob + 8) * 264 + n0) =
                    __floats2half2_rn(acc[mt][nt][2] + b1v, acc[mt][nt][3] + b1v);
            }
        }
        __syncthreads();
        #pragma unroll
        for (int p = 0; p < 8; p++) {
            int idx = t + p * 256;
            int o = idx >> 5, q8 = idx & 31;
            *(uint4*)(g_vh + ((size_t)(b * CHN + o0l + o)) * HWSZ + hw0 + q8 * 8) =
                *(const uint4*)(stg + o * 264 + q8 * 8);
        }
    }
}

// ---------------------------------------------------------------------------
// K2: fused flash attention. CTA = 128 q-rows x full j sweep (64-wide tiles).
// Warp w owns rows 16w..16w+15. Q frags register-resident; S->P in registers;
// O accumulated fp32 in regs with online-softmax rescale. grid (32, 4).
// smem: Q [128][72] @0, then 2 x (K [64][72] + V [256][72]).
// ---------------------------------------------------------------------------
constexpr int FA_QS  = 128 * 72;            // 9216 halves
constexpr int FA_KS  = 64 * 72;             // 4608 halves
constexpr int FA_VS  = 256 * 72;            // 18432 halves
constexpr int FA_BUF = FA_KS + FA_VS;       // 23040 halves
static constexpr int FA_SMEM = (FA_QS + 2 * FA_BUF) * 2;   // 110592 B

__global__ __launch_bounds__(256, 1)
void fused_attn(float* __restrict__ out)
{
    extern __shared__ char smraw[];
    const uint32_t sb = smem_u32(smraw);

    const int t = threadIdx.x;
    const int w = t >> 5, lane = t & 31, g = lane >> 2, tq = lane & 3;
    const int r8 = lane & 7, q4d = lane >> 3;
    const int i0 = blockIdx.x * 128;
    const int b  = blockIdx.y;

    const __half* Qb = g_qh + ((size_t)(b * HWSZ + i0)) * CQKD;
    const __half* Kb = g_kh + (size_t)b * HWSZ * CQKD;
    const __half* Vb = g_vh + (size_t)b * CHN * HWSZ;

    // Q tile -> smem (group 0)
    #pragma unroll
    for (int p = 0; p < 4; p++) {
        int idx = t + p * 256;
        int row = idx >> 3, q8 = idx & 7;
        cpa16(sb + (uint32_t)(row * 72 + q8 * 8) * 2, Qb + (size_t)row * CQKD + q8 * 8);
    }
    asm volatile("cp.async.commit_group;" ::: "memory");

    auto load_kv = [&](int jt, int buf) {
        uint32_t kd = sb + (uint32_t)(FA_QS + buf * FA_BUF) * 2;
        uint32_t vd = kd + (uint32_t)FA_KS * 2;
        #pragma unroll
        for (int p = 0; p < 2; p++) {               // K: 64 x 64
            int idx = t + p * 256;
            int row = idx >> 3, q8 = idx & 7;
            cpa16(kd + (uint32_t)(row * 72 + q8 * 8) * 2,
                  Kb + ((size_t)(jt * 64 + row)) * CQKD + q8 * 8);
        }
        #pragma unroll
        for (int p = 0; p < 8; p++) {               // V: 256 x 64
            int idx = t + p * 256;
            int row = idx >> 3, q8 = idx & 7;
            cpa16(vd + (uint32_t)(row * 72 + q8 * 8) * 2,
                  Vb + (size_t)row * HWSZ + jt * 64 + q8 * 8);
        }
        asm volatile("cp.async.commit_group;" ::: "memory");
    };

    load_kv(0, 0);
    asm volatile("cp.async.wait_group 1;" ::: "memory");   // Q ready
    __syncthreads();

    // register-resident Q fragments (rows 16w..16w+15, 4 ksteps of d)
    uint32_t qf[4][4];
    #pragma unroll
    for (int s = 0; s < 4; s++) {
        int row = 16 * w + r8 + (q4d & 1) * 8;
        uint32_t addr = sb + (uint32_t)(row * 72 + 16 * s + (q4d >> 1) * 8) * 2;
        ldsm4(qf[s][0], qf[s][1], qf[s][2], qf[s][3], addr);
    }

    float oacc[32][4];
    #pragma unroll
    for (int nt = 0; nt < 32; nt++)
        #pragma unroll
        for (int e = 0; e < 4; e++) oacc[nt][e] = 0.f;
    float m0 = -1e30f, m1 = -1e30f, l0 = 0.f, l1 = 0.f;

    for (int jt = 0; jt < 64; jt++) {
        const int buf = jt & 1;
        if (jt + 1 < 64) {
            load_kv(jt + 1, buf ^ 1);
            asm volatile("cp.async.wait_group 1;" ::: "memory");
        } else {
            asm volatile("cp.async.wait_group 0;" ::: "memory");
        }
        __syncthreads();

        const uint32_t kd = sb + (uint32_t)(FA_QS + buf * FA_BUF) * 2;
        const uint32_t vd = kd + (uint32_t)FA_KS * 2;

        // ---- S = Q K^T (16 rows x 64 j per warp) ----
        float sacc[8][4];
        #pragma unroll
        for (int nt = 0; nt < 8; nt++)
            #pragma unroll
            for (int e = 0; e < 4; e++) sacc[nt][e] = 0.f;

        #pragma unroll
        for (int s = 0; s < 4; s++) {
            #pragma unroll
            for (int np = 0; np < 4; np++) {
                int row = np * 16 + ((lane >> 4) * 8) + r8;
                uint32_t addr = kd + (uint32_t)(row * 72 + 16 * s + ((lane >> 3) & 1) * 8) * 2;
                uint32_t b0, b1, b2, b3;
                ldsm4(b0, b1, b2, b3, addr);
                mma16(sacc[2 * np],     qf[s], b0, b1);
                mma16(sacc[2 * np + 1], qf[s], b2, b3);
            }
        }

        // ---- online softmax (rows g, g+8 within warp's 16) ----
        float mx0 = sacc[0][0], mx1 = sacc[0][2];
        #pragma unroll
        for (int nt = 0; nt < 8; nt++) {
            mx0 = fmaxf(mx0, fmaxf(sacc[nt][0], sacc[nt][1]));
            mx1 = fmaxf(mx1, fmaxf(sacc[nt][2], sacc[nt][3]));
        }
        mx0 = fmaxf(mx0, __shfl_xor_sync(~0u, mx0, 1));
        mx0 = fmaxf(mx0, __shfl_xor_sync(~0u, mx0, 2));
        mx1 = fmaxf(mx1, __shfl_xor_sync(~0u, mx1, 1));
        mx1 = fmaxf(mx1, __shfl_xor_sync(~0u, mx1, 2));
        const float mn0 = fmaxf(m0, mx0), mn1 = fmaxf(m1, mx1);
        const float a0 = __expf(m0 - mn0), a1 = __expf(m1 - mn1);
        m0 = mn0; m1 = mn1;

        uint32_t pf[4][4];
        float s0 = 0.f, s1 = 0.f;
        #pragma unroll
        for (int nt = 0; nt < 8; nt++) {
            float e0 = __expf(sacc[nt][0] - mn0);
            float e1 = __expf(sacc[nt][1] - mn0);
            float e2 = __expf(sacc[nt][2] - mn1);
            float e3 = __expf(sacc[nt][3] - mn1);
            s0 += e0 + e1; s1 += e2 + e3;
            int s = nt >> 1, hi = nt & 1;
            pf[s][hi ? 2 : 0] = h2bits(__floats2half2_rn(e0, e1));
            pf[s][hi ? 3 : 1] = h2bits(__floats2half2_rn(e2, e3));
        }
        s0 += __shfl_xor_sync(~0u, s0, 1);
        s0 += __shfl_xor_sync(~0u, s0, 2);
        s1 += __shfl_xor_sync(~0u, s1, 1);
        s1 += __shfl_xor_sync(~0u, s1, 2);
        l0 = l0 * a0 + s0;
        l1 = l1 * a1 + s1;

        // ---- rescale O, then O += P V^T ----
        #pragma unroll
        for (int nt = 0; nt < 32; nt++) {
            oacc[nt][0] *= a0; oacc[nt][1] *= a0;
            oacc[nt][2] *= a1; oacc[nt][3] *= a1;
        }
        #pragma unroll
        for (int s = 0; s < 4; s++) {
            #pragma unroll
            for (int np = 0; np < 16; np++) {
                int row = np * 16 + ((lane >> 4) * 8) + r8;
                uint32_t addr = vd + (uint32_t)(row * 72 + 16 * s + ((lane >> 3) & 1) * 8) * 2;
                uint32_t b0, b1, b2, b3;
                ldsm4(b0, b1, b2, b3, addr);
                mma16(oacc[2 * np],     pf[s], b0, b1);
                mma16(oacc[2 * np + 1], pf[s], b2, b3);
            }
        }
        __syncthreads();
    }

    // ---- epilogue: normalize, transpose via smem, coalesced stores ----
    const float rl0 = 1.f / l0, rl1 = 1.f / l1;
    float* stg = (float*)smraw;                 // [128 c][132 i]
    for (int h = 0; h < 2; h++) {
        __syncthreads();
        const int il = 16 * w;
        #pragma unroll
        for (int ntl = 0; ntl < 16; ntl++) {
            int nt = h * 16 + ntl;
            int cl = ntl * 8 + 2 * tq;
            stg[cl * 132 + il + g]           = oacc[nt][0] * rl0;
            stg[(cl + 1) * 132 + il + g]     = oacc[nt][1] * rl0;
            stg[cl * 132 + il + g + 8]       = oacc[nt][2] * rl1;
            stg[(cl + 1) * 132 + il + g + 8] = oacc[nt][3] * rl1;
        }
        __syncthreads();
        float* dst = out + ((size_t)(b * CHN + h * 128)) * HWSZ + i0;
        #pragma unroll
        for (int p = 0; p < 16; p++) {
            int idx = t + p * 256;
            int c = idx >> 5, q4 = idx & 31;
            *(float4*)(dst + (size_t)c * HWSZ + 4 * q4) =
                *(const float4*)(stg + c * 132 + 4 * q4);
        }
    }
}

// ---------------------------------------------------------------------------

static constexpr int CONV_SMEM = 2 * CBUF16 * 2;                 // 94464 B

extern "C" void kernel_launch(void* const* d_in, const int* in_sizes, int n_in,
                              void* d_out, int out_size)
{
    const float* x   = (const float*)d_in[0];
    const float* q_w = (const float*)d_in[1];
    const float* q_b = (const float*)d_in[2];
    const float* k_w = (const float*)d_in[3];
    const float* k_b = (const float*)d_in[4];
    const float* v_w = (const float*)d_in[5];
    const float* v_b = (const float*)d_in[6];
    float* out = (float*)d_out;

    cudaFuncSetAttribute(conv3x3_tc, cudaFuncAttributeMaxDynamicSharedMemorySize, CONV_SMEM);
    cudaFuncSetAttribute(fused_attn, cudaFuncAttributeMaxDynamicSharedMemorySize, FA_SMEM);

    cvt_x<<<1024, 256>>>(x);
    cvt_w<<<384, 256>>>(q_w, k_w, v_w);
    conv3x3_tc<<<dim3(16, 24), 256, CONV_SMEM>>>(q_b, k_b, v_b);
    fused_attn<<<dim3(HWSZ / 128, BATCH), 256, FA_SMEM>>>(out);
}